// round 9
// baseline (speedup 1.0000x reference)
#include <cuda_runtime.h>
#include <cuda_bf16.h>
#include <math.h>
#include <stdint.h>

#define BB   8
#define NN   4096
#define SS   1024
#define KNBR 16
#define CIN  128
#define COUT 256
#define MROWS (BB*SS*KNBR)   /* 131072 */
#define BSR   (BB*SS)        /* 8192  */
#define NPTS  (BB*NN)        /* 32768 */

typedef __nv_bfloat16 bf16;

// ---------------- static device scratch (no allocs allowed) ----------------
__device__ float g_pos [(size_t)MROWS*COUT];
__device__ bf16  g_a1h [(size_t)MROWS*COUT];
__device__ bf16  g_a1l [(size_t)MROWS*COUT];
__device__ bf16  g_x1h [(size_t)MROWS*COUT];   // h1 then h2
__device__ bf16  g_x1l [(size_t)MROWS*COUT];
__device__ bf16  g_ph  [(size_t)NPTS*CIN];
__device__ bf16  g_pl  [(size_t)NPTS*CIN];
__device__ float g_kall[(size_t)NPTS*COUT];
__device__ float g_vall[(size_t)NPTS*COUT];
__device__ float g_q   [(size_t)BSR*COUT];
__device__ bf16  g_r0h [(size_t)BSR*COUT];
__device__ bf16  g_r0l [(size_t)BSR*COUT];
__device__ float g_res1[(size_t)BSR*COUT];
__device__ int   g_fps [BSR];
__device__ int   g_knn [MROWS];
__device__ float g_psum[64*COUT];
__device__ float g_psq [64*COUT];
__device__ float g_scale[COUT];
__device__ float g_shift[COUT];
// pre-split weights
__device__ bf16  g_wkh[CIN*COUT],  g_wkl[CIN*COUT];
__device__ bf16  g_wvh[CIN*COUT],  g_wvl[CIN*COUT];
__device__ bf16  g_wqh[CIN*COUT],  g_wql[CIN*COUT];
__device__ bf16  g_dw2h[COUT*COUT], g_dw2l[COUT*COUT];
__device__ bf16  g_gw1h[COUT*COUT], g_gw1l[COUT*COUT];
__device__ bf16  g_gw2h[COUT*COUT], g_gw2l[COUT*COUT];
__device__ bf16  g_lwh[COUT*COUT],  g_lwl[COUT*COUT];

// -------------------- bf16 split helper ------------------------------------
__device__ __forceinline__ void split2(float x0, float x1, uint32_t& hi, uint32_t& lo)
{
    bf16 h0 = __float2bfloat16(x0);
    bf16 h1 = __float2bfloat16(x1);
    float r0 = __fsub_rn(x0, __bfloat162float(h0));
    float r1 = __fsub_rn(x1, __bfloat162float(h1));
    bf16 l0 = __float2bfloat16(r0);
    bf16 l1 = __float2bfloat16(r1);
    hi = (uint32_t)__bfloat16_as_ushort(h0) | ((uint32_t)__bfloat16_as_ushort(h1) << 16);
    lo = (uint32_t)__bfloat16_as_ushort(l0) | ((uint32_t)__bfloat16_as_ushort(l1) << 16);
}

// ---------------------------- FPS -----------------------------------------
__global__ __launch_bounds__(256) void fps_kernel(const float* __restrict__ xyz,
                                                  float* __restrict__ newxyz)
{
    __shared__ float sx[NN], sy[NN], sz[NN];
    __shared__ unsigned long long swk[2][8];

    int b   = blockIdx.x;
    int tid = threadIdx.x;
    int lane = tid & 31, wid = tid >> 5;
    const float* base = xyz + (size_t)b * NN * 3;

    for (int i = tid; i < NN; i += 256) {
        sx[i] = base[i*3+0];
        sy[i] = base[i*3+1];
        sz[i] = base[i*3+2];
    }
    __syncthreads();

    float px[16], py[16], pz[16], dist[16];
#pragma unroll
    for (int j = 0; j < 16; j++) {
        int i = tid * 16 + j;
        px[j] = sx[i]; py[j] = sy[i]; pz[j] = sz[i];
        dist[j] = 1e10f;
    }

    int far = 0;
    for (int s = 0; s < SS; s++) {
        float cx = sx[far], cy = sy[far], cz = sz[far];
        if (tid == 0) {
            g_fps[b*SS + s] = b*NN + far;
            newxyz[((size_t)b*SS + s)*3 + 0] = cx;
            newxyz[((size_t)b*SS + s)*3 + 1] = cy;
            newxyz[((size_t)b*SS + s)*3 + 2] = cz;
        }
        float bv = -1.0f; int bi = 0;
#pragma unroll
        for (int j = 0; j < 16; j++) {
            float dx = __fsub_rn(px[j], cx);
            float dy = __fsub_rn(py[j], cy);
            float dz = __fsub_rn(pz[j], cz);
            float d  = __fadd_rn(__fadd_rn(__fmul_rn(dx,dx), __fmul_rn(dy,dy)),
                                 __fmul_rn(dz,dz));
            dist[j] = fminf(dist[j], d);
            if (dist[j] > bv) { bv = dist[j]; bi = tid*16 + j; }
        }
        unsigned key  = __float_as_uint(bv);
        unsigned wmax = __reduce_max_sync(0xffffffffu, key);
        unsigned ball = __ballot_sync(0xffffffffu, key == wmax);
        int src  = __ffs(ball) - 1;
        int wbi  = __shfl_sync(0xffffffffu, bi, src);
        if (lane == 0)
            swk[s & 1][wid] = ((unsigned long long)wmax << 32)
                            | (unsigned)(NN - 1 - wbi);
        __syncthreads();
        unsigned long long best = swk[s & 1][0];
#pragma unroll
        for (int w = 1; w < 8; w++) {
            unsigned long long c = swk[s & 1][w];
            if (c > best) best = c;
        }
        far = NN - 1 - (int)(best & 0xffffffffu);
    }
}

// ---------------------------- KNN (smem-staged) ----------------------------
__global__ __launch_bounds__(256) void knn_kernel(const float* __restrict__ xyz,
                                                  const float* __restrict__ newxyz)
{
    __shared__ float sx[NN], sy[NN], sz[NN];

    int warp = (blockIdx.x * blockDim.x + threadIdx.x) >> 5;
    int lane = threadIdx.x & 31;
    int wloc = threadIdx.x >> 5;
    int b = warp / SS;                      // all warps in block share b (8 | 1024)
    const float* base = xyz + (size_t)b * NN * 3;

    for (int i = threadIdx.x; i < NN; i += 256) {
        sx[i] = base[i*3+0];
        sy[i] = base[i*3+1];
        sz[i] = base[i*3+2];
    }
    __syncthreads();

    float nx = newxyz[(size_t)warp*3+0];
    float ny = newxyz[(size_t)warp*3+1];
    float nz = newxyz[(size_t)warp*3+2];
    float ns = fmaf(nz, nz, fmaf(ny, ny, __fmul_rn(nx, nx)));

    float v[16]; int id[16];
#pragma unroll
    for (int t = 0; t < 16; t++) { v[t] = 3.4e38f; id[t] = 0x7fffffff; }

    for (int j = lane; j < NN; j += 32) {
        float x = sx[j], y = sy[j], z = sz[j];
        float dot = fmaf(z, nz, fmaf(y, ny, __fmul_rn(x, nx)));
        float nq  = fmaf(z, z,  fmaf(y, y,  __fmul_rn(x, x)));
        float d   = __fadd_rn(__fsub_rn(ns, __fmul_rn(2.0f, dot)), nq);
        if (d < v[15]) {
            v[15] = d; id[15] = j;
#pragma unroll
            for (int t = 15; t > 0; t--) {
                if (v[t] < v[t-1] || (v[t] == v[t-1] && id[t] < id[t-1])) {
                    float tv = v[t]; v[t] = v[t-1]; v[t-1] = tv;
                    int   ti = id[t]; id[t] = id[t-1]; id[t-1] = ti;
                } else break;
            }
        }
    }

    __shared__ float smd[8][512];
    __shared__ int   smi[8][512];
#pragma unroll
    for (int t = 0; t < 16; t++) {
        smd[wloc][lane*16 + t] = v[t];
        smi[wloc][lane*16 + t] = id[t];
    }
    __syncwarp();

    int p = 0;
    for (int t = 0; t < 16; t++) {
        float cv = (p < 16) ? smd[wloc][lane*16 + p] : 3.4e38f;
        int   ci = (p < 16) ? smi[wloc][lane*16 + p] : 0x7fffffff;
        float mv = cv; int mi = ci;
#pragma unroll
        for (int off = 16; off; off >>= 1) {
            float ov = __shfl_xor_sync(0xffffffffu, mv, off);
            int   oi = __shfl_xor_sync(0xffffffffu, mi, off);
            if (ov < mv || (ov == mv && oi < mi)) { mv = ov; mi = oi; }
        }
        if (cv == mv && ci == mi) p++;
        if (lane == 0) g_knn[(size_t)warp*16 + t] = b*NN + mi;
        __syncwarp();
    }
}

// -------------------- fp32 -> bf16 hi/lo conversion -------------------------
__global__ void cvt_kernel(const float* __restrict__ src,
                           bf16* __restrict__ hi, bf16* __restrict__ lo, int n)
{
    int e = (blockIdx.x * blockDim.x + threadIdx.x) * 2;
    if (e >= n) return;
    uint32_t h, l;
    split2(src[e], src[e+1], h, l);
    *(uint32_t*)&hi[e] = h;
    *(uint32_t*)&lo[e] = l;
}

// ------------------------- mma helpers --------------------------------------
__device__ __forceinline__ void cp16(void* s, const void* g)
{
    unsigned sa = (unsigned)__cvta_generic_to_shared(s);
    asm volatile("cp.async.ca.shared.global [%0], [%1], 16;\n" :: "r"(sa), "l"(g));
}
#define CP_COMMIT() asm volatile("cp.async.commit_group;\n")

__device__ __forceinline__ void ldsm_x4(uint32_t* r, const void* p)
{
    uint32_t a = (uint32_t)__cvta_generic_to_shared(p);
    asm volatile("ldmatrix.sync.aligned.m8n8.x4.shared.b16 {%0,%1,%2,%3}, [%4];"
                 : "=r"(r[0]), "=r"(r[1]), "=r"(r[2]), "=r"(r[3]) : "r"(a));
}

__device__ __forceinline__ void ldsm_x4_t(uint32_t* r, const void* p)
{
    uint32_t a = (uint32_t)__cvta_generic_to_shared(p);
    asm volatile("ldmatrix.sync.aligned.m8n8.x4.trans.shared.b16 {%0,%1,%2,%3}, [%4];"
                 : "=r"(r[0]), "=r"(r[1]), "=r"(r[2]), "=r"(r[3]) : "r"(a));
}

__device__ __forceinline__ void mma16816(float* c, const uint32_t* a, const uint32_t* b)
{
    asm volatile("mma.sync.aligned.m16n8k16.row.col.f32.bf16.bf16.f32 "
                 "{%0,%1,%2,%3}, {%4,%5,%6,%7}, {%8,%9}, {%0,%1,%2,%3};"
                 : "+f"(c[0]), "+f"(c[1]), "+f"(c[2]), "+f"(c[3])
                 : "r"(a[0]), "r"(a[1]), "r"(a[2]), "r"(a[3]),
                   "r"(b[0]), "r"(b[1]));
}

// ----------------------- shared GEMM mainloop macro -------------------------
#define KCH    16
#define NSTG   4
#define ASTR2  24
#define BSTR2  72
#define AS_BYTES  (NSTG*2*128*ASTR2*2)
#define BS_BYTES  (NSTG*2*KCH*BSTR2*2)
#define TG_SMEM   (AS_BYTES + BS_BYTES + 512)

// declares/fills: acc[2][4][4]; uses tid,m0,n0,Kd and operand pointers.
#define GEMM_MAINLOOP(AHI, ALO, ROWMAP, WHI, WLO)                               \
    extern __shared__ char smraw[];                                            \
    typedef bf16 (*AsT)[2][128][ASTR2];                                        \
    typedef bf16 (*BsT)[2][KCH][BSTR2];                                        \
    AsT As = (AsT)smraw;                                                       \
    BsT Bs = (BsT)(smraw + AS_BYTES);                                          \
    int* rmap = (int*)(smraw + AS_BYTES + BS_BYTES);                           \
    if (tid < 128) rmap[tid] = (ROWMAP) ? (ROWMAP)[m0 + tid] : (m0 + tid);     \
    __syncthreads();                                                           \
    const int arow = tid >> 1;                                                 \
    const int ach  = (tid & 1) * 8;                                            \
    const bf16* aSrcH = (AHI) + (size_t)rmap[arow] * Kd + ach;                 \
    const bf16* aSrcL = (ALO) + (size_t)rmap[arow] * Kd + ach;                 \
    const int bpl = tid >> 7;                                                  \
    const int bk  = (tid >> 3) & 15;                                           \
    const int bch = (tid & 7) * 8;                                             \
    const bf16* bSrc = (bpl ? (WLO) : (WHI)) + (size_t)bk * COUT + n0 + bch;   \
    const int lane = tid & 31;                                                 \
    const int wm = (tid >> 5) >> 1;                                            \
    const int wn = (tid >> 5) & 1;                                             \
    const int aFrow = wm * 32 + (lane & 15);                                   \
    const int aFk   = (lane >> 4) * 8;                                         \
    const int bFk   = (lane & 7) + ((lane >> 3) & 1) * 8;                      \
    const int bFn   = (lane >> 4) * 8;                                         \
    float acc[2][4][4];                                                        \
    _Pragma("unroll")                                                          \
    for (int i = 0; i < 2; i++)                                                \
        _Pragma("unroll")                                                      \
        for (int j = 0; j < 4; j++)                                            \
            _Pragma("unroll")                                                  \
            for (int l = 0; l < 4; l++) acc[i][j][l] = 0.0f;                   \
    const int nk = Kd >> 4;                                                    \
    _Pragma("unroll")                                                          \
    for (int s = 0; s < NSTG - 1; s++) {                                       \
        if (s < nk) {                                                          \
            int k0 = s * KCH;                                                  \
            cp16(&As[s][0][arow][ach], aSrcH + k0);                            \
            cp16(&As[s][1][arow][ach], aSrcL + k0);                            \
            cp16(&Bs[s][bpl][bk][bch], bSrc + (size_t)k0 * COUT);              \
        }                                                                      \
        CP_COMMIT();                                                           \
    }                                                                          \
    for (int t = 0; t < nk; t++) {                                             \
        const int cur = t & (NSTG - 1);                                        \
        if (t + NSTG - 1 < nk) {                                               \
            asm volatile("cp.async.wait_group 2;\n" ::: "memory");             \
        } else {                                                               \
            asm volatile("cp.async.wait_group 0;\n" ::: "memory");             \
        }                                                                      \
        __syncthreads();                                                       \
        if (t + NSTG - 1 < nk) {                                               \
            const int stg = (t + NSTG - 1) & (NSTG - 1);                       \
            const int k0  = (t + NSTG - 1) * KCH;                              \
            cp16(&As[stg][0][arow][ach], aSrcH + k0);                          \
            cp16(&As[stg][1][arow][ach], aSrcL + k0);                          \
            cp16(&Bs[stg][bpl][bk][bch], bSrc + (size_t)k0 * COUT);            \
            CP_COMMIT();                                                       \
        }                                                                      \
        uint32_t ah[2][4], al[2][4], bh[4][2], bl[4][2];                       \
        _Pragma("unroll")                                                      \
        for (int mt = 0; mt < 2; mt++) {                                       \
            ldsm_x4(ah[mt], &As[cur][0][aFrow + mt*16][aFk]);                  \
            ldsm_x4(al[mt], &As[cur][1][aFrow + mt*16][aFk]);                  \
        }                                                                      \
        _Pragma("unroll")                                                      \
        for (int g = 0; g < 2; g++) {                                          \
            uint32_t tmp[4];                                                   \
            ldsm_x4_t(tmp, &Bs[cur][0][bFk][wn*32 + g*16 + bFn]);              \
            bh[g*2][0]   = tmp[0]; bh[g*2][1]   = tmp[1];                      \
            bh[g*2+1][0] = tmp[2]; bh[g*2+1][1] = tmp[3];                      \
            ldsm_x4_t(tmp, &Bs[cur][1][bFk][wn*32 + g*16 + bFn]);              \
            bl[g*2][0]   = tmp[0]; bl[g*2][1]   = tmp[1];                      \
            bl[g*2+1][0] = tmp[2]; bl[g*2+1][1] = tmp[3];                      \
        }                                                                      \
        _Pragma("unroll")                                                      \
        for (int mt = 0; mt < 2; mt++)                                         \
            _Pragma("unroll")                                                  \
            for (int nt = 0; nt < 4; nt++) {                                   \
                mma16816(acc[mt][nt], ah[mt], bh[nt]);                         \
                mma16816(acc[mt][nt], al[mt], bh[nt]);                         \
                mma16816(acc[mt][nt], ah[mt], bl[nt]);                         \
            }                                                                  \
    }

// --------- generic GEMM (optionally dual weight set / dual output) ----------
__global__ __launch_bounds__(256, 2) void tgemm_bf(
    const bf16* __restrict__ Ahi, const bf16* __restrict__ Alo,
    const int* __restrict__ rowmap,
    const bf16* __restrict__ Whi, const bf16* __restrict__ Wlo,
    const bf16* __restrict__ W2hi, const bf16* __restrict__ W2lo,
    const float* __restrict__ bias, int Kd, int relu,
    float* __restrict__ C, float* __restrict__ Cb,
    bf16* __restrict__ Chi, bf16* __restrict__ Clo,
    const float* __restrict__ qv, const float* __restrict__ kall,
    const int* __restrict__ knn,
    bf16* __restrict__ A1hi, bf16* __restrict__ A1lo)
{
    const int tid = threadIdx.x;
    const int m0  = blockIdx.y * 128;
    int bx = blockIdx.x;
    const bf16 *WhiS = Whi, *WloS = Wlo;
    float* CS = C;
    if (W2hi && bx >= (int)(gridDim.x >> 1)) {
        WhiS = W2hi; WloS = W2lo; CS = Cb; bx -= (gridDim.x >> 1);
    }
    const int n0 = bx * 64;

    GEMM_MAINLOOP(Ahi, Alo, rowmap, WhiS, WloS)

    const int quad = lane >> 2, tq = lane & 3;
#pragma unroll
    for (int mt = 0; mt < 2; mt++) {
        int r0 = m0 + wm*32 + mt*16 + quad;
        int r1 = r0 + 8;
        const float *q0 = nullptr, *k0p = nullptr, *q1 = nullptr, *k1p = nullptr;
        if (A1hi) {
            q0 = qv + (size_t)(r0 >> 4) * COUT;  k0p = kall + (size_t)knn[r0] * COUT;
            q1 = qv + (size_t)(r1 >> 4) * COUT;  k1p = kall + (size_t)knn[r1] * COUT;
        }
#pragma unroll
        for (int nt = 0; nt < 4; nt++) {
            int col = n0 + wn*32 + nt*8 + tq*2;
            float o0 = acc[mt][nt][0], o1 = acc[mt][nt][1];
            float o2 = acc[mt][nt][2], o3 = acc[mt][nt][3];
            if (bias) { float bb0 = bias[col], bb1 = bias[col+1];
                        o0 += bb0; o1 += bb1; o2 += bb0; o3 += bb1; }
            if (relu) { o0 = fmaxf(o0,0.f); o1 = fmaxf(o1,0.f);
                        o2 = fmaxf(o2,0.f); o3 = fmaxf(o3,0.f); }
            if (CS) {
                *(float2*)(CS + (size_t)r0*COUT + col) = make_float2(o0, o1);
                *(float2*)(CS + (size_t)r1*COUT + col) = make_float2(o2, o3);
            }
            if (Chi) {
                uint32_t h, l;
                split2(o0, o1, h, l);
                *(uint32_t*)&Chi[(size_t)r0*COUT + col] = h;
                *(uint32_t*)&Clo[(size_t)r0*COUT + col] = l;
                split2(o2, o3, h, l);
                *(uint32_t*)&Chi[(size_t)r1*COUT + col] = h;
                *(uint32_t*)&Clo[(size_t)r1*COUT + col] = l;
            }
            if (A1hi) {
                float w0 = __fadd_rn(__fsub_rn(q0[col],   k0p[col]),   o0);
                float w1 = __fadd_rn(__fsub_rn(q0[col+1], k0p[col+1]), o1);
                float w2 = __fadd_rn(__fsub_rn(q1[col],   k1p[col]),   o2);
                float w3 = __fadd_rn(__fsub_rn(q1[col+1], k1p[col+1]), o3);
                uint32_t h, l;
                split2(w0, w1, h, l);
                *(uint32_t*)&A1hi[(size_t)r0*COUT + col] = h;
                *(uint32_t*)&A1lo[(size_t)r0*COUT + col] = l;
                split2(w2, w3, h, l);
                *(uint32_t*)&A1hi[(size_t)r1*COUT + col] = h;
                *(uint32_t*)&A1lo[(size_t)r1*COUT + col] = l;
            }
        }
    }
}

// --------- att GEMM with fused per-channel softmax + weighted sum -----------
// computes att = A@gw2 + gb2 then per 16-row group g (one sampled point):
//   p = softmax(att/16, over group rows); r0[g] = sum_i p_i * (vall[knn] + pos)
__global__ __launch_bounds__(256, 2) void tgemm_att(
    const bf16* __restrict__ Ahi, const bf16* __restrict__ Alo,
    const bf16* __restrict__ Whi, const bf16* __restrict__ Wlo,
    const float* __restrict__ bias, int Kd,
    const int* __restrict__ knn,
    const float* __restrict__ pos, const float* __restrict__ vall,
    bf16* __restrict__ R0hi, bf16* __restrict__ R0lo)
{
    const int tid = threadIdx.x;
    const int m0  = blockIdx.y * 128;
    const int n0  = blockIdx.x * 64;
    const int* rowmap = nullptr;

    GEMM_MAINLOOP(Ahi, Alo, rowmap, Whi, Wlo)

    const int quad = lane >> 2;
    const unsigned FULL = 0xffffffffu;
#pragma unroll
    for (int mt = 0; mt < 2; mt++) {
        int gr  = m0 + wm*32 + mt*16;      // 16-aligned group base
        int bs  = gr >> 4;
        int ra  = gr + quad;
        int rb  = ra + 8;
        int kna = knn[ra], knb = knn[rb];
#pragma unroll
        for (int nt = 0; nt < 4; nt++) {
            int col = n0 + wn*32 + nt*8 + (lane & 3)*2;
            float b0 = bias[col], b1 = bias[col+1];
            float v00 = (acc[mt][nt][0] + b0) * 0.0625f;   // row ra, col
            float v01 = (acc[mt][nt][1] + b1) * 0.0625f;   // row ra, col+1
            float v10 = (acc[mt][nt][2] + b0) * 0.0625f;   // row rb, col
            float v11 = (acc[mt][nt][3] + b1) * 0.0625f;   // row rb, col+1
            // per-column max over the 16 group rows (2 local + quad lanes)
            float m0c = fmaxf(v00, v10);
            float m1c = fmaxf(v01, v11);
#pragma unroll
            for (int off = 4; off <= 16; off <<= 1) {
                m0c = fmaxf(m0c, __shfl_xor_sync(FULL, m0c, off));
                m1c = fmaxf(m1c, __shfl_xor_sync(FULL, m1c, off));
            }
            float e00 = expf(v00 - m0c), e10 = expf(v10 - m0c);
            float e01 = expf(v01 - m1c), e11 = expf(v11 - m1c);
            float s0 = e00 + e10, s1 = e01 + e11;
#pragma unroll
            for (int off = 4; off <= 16; off <<= 1) {
                s0 += __shfl_xor_sync(FULL, s0, off);
                s1 += __shfl_xor_sync(FULL, s1, off);
            }
            float2 pa = *(const float2*)(pos  + (size_t)ra*COUT + col);
            float2 pb = *(const float2*)(pos  + (size_t)rb*COUT + col);
            float2 va = *(const float2*)(vall + (size_t)kna*COUT + col);
            float2 vb = *(const float2*)(vall + (size_t)knb*COUT + col);
            float w0 = e00*(va.x + pa.x) + e10*(vb.x + pb.x);
            float w1 = e01*(va.y + pa.y) + e11*(vb.y + pb.y);
#pragma unroll
            for (int off = 4; off <= 16; off <<= 1) {
                w0 += __shfl_xor_sync(FULL, w0, off);
                w1 += __shfl_xor_sync(FULL, w1, off);
            }
            if (quad == 0) {
                float o0 = w0 / s0, o1 = w1 / s1;
                uint32_t h, l;
                split2(o0, o1, h, l);
                *(uint32_t*)&R0hi[(size_t)bs*COUT + col] = h;
                *(uint32_t*)&R0lo[(size_t)bs*COUT + col] = l;
            }
        }
    }
}

// ------------------ pos-enc layer 1 (3 -> 256, relu, bf16 split out) --------
__global__ void h1_kernel(const float* __restrict__ xyz, const float* __restrict__ newxyz,
                          const float* __restrict__ dw1, const float* __restrict__ db1)
{
    int r = blockIdx.x;
    int c = threadIdx.x * 2;
    int g  = g_knn[r];
    int bs = r >> 4;
    float cx = xyz[(size_t)g*3+0] - newxyz[(size_t)bs*3+0];
    float cy = xyz[(size_t)g*3+1] - newxyz[(size_t)bs*3+1];
    float cz = xyz[(size_t)g*3+2] - newxyz[(size_t)bs*3+2];
    float h0 = db1[c],   h1v = db1[c+1];
    h0  = fmaf(cx, dw1[0*COUT + c],   h0);
    h0  = fmaf(cy, dw1[1*COUT + c],   h0);
    h0  = fmaf(cz, dw1[2*COUT + c],   h0);
    h1v = fmaf(cx, dw1[0*COUT + c+1], h1v);
    h1v = fmaf(cy, dw1[1*COUT + c+1], h1v);
    h1v = fmaf(cz, dw1[2*COUT + c+1], h1v);
    h0  = fmaxf(h0, 0.0f);
    h1v = fmaxf(h1v, 0.0f);
    uint32_t h, l;
    split2(h0, h1v, h, l);
    *(uint32_t*)&g_x1h[(size_t)r*COUT + c] = h;
    *(uint32_t*)&g_x1l[(size_t)r*COUT + c] = l;
}

// ---------------------------- BatchNorm ------------------------------------
__global__ void bn_partial_kernel()
{
    int blk = blockIdx.x;
    int c   = threadIdx.x;
    float s = 0.0f, q = 0.0f;
    for (int r = blk*128; r < blk*128 + 128; r++) {
        float x = g_res1[(size_t)r*COUT + c];
        s += x; q = fmaf(x, x, q);
    }
    g_psum[blk*COUT + c] = s;
    g_psq [blk*COUT + c] = q;
}

__global__ void bn_final_kernel(const float* __restrict__ bng, const float* __restrict__ bnb)
{
    int c = threadIdx.x;
    float s = 0.0f, q = 0.0f;
    for (int i = 0; i < 64; i++) { s += g_psum[i*COUT + c]; q += g_psq[i*COUT + c]; }
    float mean = s * (1.0f/(float)BSR);
    float var  = fmaxf(q * (1.0f/(float)BSR) - mean*mean, 0.0f);
    float sc   = bng[c] * rsqrtf(var + 1e-5f);
    g_scale[c] = sc;
    g_shift[c] = bnb[c] - mean * sc;
}

__global__ void bn_apply_kernel(float* __restrict__ out)
{
    size_t e = (size_t)blockIdx.x * blockDim.x + threadIdx.x;
    int c = (int)(e & 255);
    out[e] = fmaxf(fmaf(g_res1[e], g_scale[c], g_shift[c]), 0.0f);
}

// ------------------------------ launch --------------------------------------
extern "C" void kernel_launch(void* const* d_in, const int* in_sizes, int n_in,
                              void* d_out, int out_size)
{
    const float* xyz    = (const float*)d_in[0];
    const float* points = (const float*)d_in[1];
    const float* wq     = (const float*)d_in[2];
    const float* wk     = (const float*)d_in[3];
    const float* wv     = (const float*)d_in[4];
    const float* dw1    = (const float*)d_in[5];
    const float* db1    = (const float*)d_in[6];
    const float* dw2    = (const float*)d_in[7];
    const float* db2    = (const float*)d_in[8];
    const float* gw1    = (const float*)d_in[9];
    const float* gb1    = (const float*)d_in[10];
    const float* gw2    = (const float*)d_in[11];
    const float* gb2    = (const float*)d_in[12];
    const float* lw     = (const float*)d_in[13];
    const float* lb     = (const float*)d_in[14];
    const float* bng    = (const float*)d_in[15];
    const float* bnb    = (const float*)d_in[16];

    float* out     = (float*)d_out;
    float* newxyz  = out;
    float* res_out = out + (size_t)BSR*3;

    static bool attr_set = false;
    if (!attr_set) {
        cudaFuncSetAttribute(tgemm_bf,  cudaFuncAttributeMaxDynamicSharedMemorySize, TG_SMEM);
        cudaFuncSetAttribute(tgemm_att, cudaFuncAttributeMaxDynamicSharedMemorySize, TG_SMEM);
        attr_set = true;
    }

#define SYM(p, s) void* p; cudaGetSymbolAddress(&p, s)
    SYM(ppos, g_pos);
    SYM(pa1h, g_a1h);  SYM(pa1l, g_a1l);
    SYM(px1h, g_x1h);  SYM(px1l, g_x1l);
    SYM(pph,  g_ph);   SYM(ppl,  g_pl);
    SYM(pk,   g_kall); SYM(pv,   g_vall);
    SYM(pq,   g_q);
    SYM(pr0h, g_r0h);  SYM(pr0l, g_r0l);
    SYM(pr1,  g_res1);
    SYM(pfps, g_fps);  SYM(pknn, g_knn);
    SYM(pwkh, g_wkh);  SYM(pwkl, g_wkl);
    SYM(pwvh, g_wvh);  SYM(pwvl, g_wvl);
    SYM(pwqh, g_wqh);  SYM(pwql, g_wql);
    SYM(pdw2h, g_dw2h); SYM(pdw2l, g_dw2l);
    SYM(pgw1h, g_gw1h); SYM(pgw1l, g_gw1l);
    SYM(pgw2h, g_gw2h); SYM(pgw2l, g_gw2l);
    SYM(plwh, g_lwh);   SYM(plwl, g_lwl);
#undef SYM

    // ordered so launch #6 (ncu -s 5 -c 1) is the merged k/v tensor GEMM
    cvt_kernel<<<(NPTS*CIN)/512, 256>>>(points, (bf16*)pph, (bf16*)ppl, NPTS*CIN);  // 1
    cvt_kernel<<<(CIN*COUT)/512, 256>>>(wk, (bf16*)pwkh, (bf16*)pwkl, CIN*COUT);    // 2
    cvt_kernel<<<(CIN*COUT)/512, 256>>>(wv, (bf16*)pwvh, (bf16*)pwvl, CIN*COUT);    // 3
    fps_kernel<<<BB, 256>>>(xyz, newxyz);                                           // 4
    knn_kernel<<<BSR/8, 256>>>(xyz, newxyz);                                        // 5
    // 6: merged k_all / v_all = points @ [wk | wv]
    tgemm_bf<<<dim3(8, NPTS/128), 256, TG_SMEM>>>(
        (const bf16*)pph, (const bf16*)ppl, nullptr,
        (const bf16*)pwkh, (const bf16*)pwkl,
        (const bf16*)pwvh, (const bf16*)pwvl,
        nullptr, CIN, 0,
        (float*)pk, (float*)pv, nullptr, nullptr,
        nullptr, nullptr, nullptr, nullptr, nullptr);

    cvt_kernel<<<(CIN*COUT)/512, 256>>>(wq, (bf16*)pwqh, (bf16*)pwql, CIN*COUT);
    cvt_kernel<<<(COUT*COUT)/512, 256>>>(dw2, (bf16*)pdw2h, (bf16*)pdw2l, COUT*COUT);
    cvt_kernel<<<(COUT*COUT)/512, 256>>>(gw1, (bf16*)pgw1h, (bf16*)pgw1l, COUT*COUT);
    cvt_kernel<<<(COUT*COUT)/512, 256>>>(gw2, (bf16*)pgw2h, (bf16*)pgw2l, COUT*COUT);
    cvt_kernel<<<(COUT*COUT)/512, 256>>>(lw,  (bf16*)plwh,  (bf16*)plwl,  COUT*COUT);

    // q = gather(points, fps) @ wq
    tgemm_bf<<<dim3(4, BSR/128), 256, TG_SMEM>>>(
        (const bf16*)pph, (const bf16*)ppl, (const int*)pfps,
        (const bf16*)pwqh, (const bf16*)pwql, nullptr, nullptr,
        nullptr, CIN, 0,
        (float*)pq, nullptr, nullptr, nullptr,
        nullptr, nullptr, nullptr, nullptr, nullptr);
    // pos-enc layer 1 -> x1 (bf16 split)
    h1_kernel<<<MROWS, 128>>>(xyz, newxyz, dw1, db1);
    // pos = h1 @ dw2 + db2 (fp32) + fused a1 = q - k_gather + pos (bf16 split)
    tgemm_bf<<<dim3(4, MROWS/128), 256, TG_SMEM>>>(
        (const bf16*)px1h, (const bf16*)px1l, nullptr,
        (const bf16*)pdw2h, (const bf16*)pdw2l, nullptr, nullptr,
        db2, COUT, 0,
        (float*)ppos, nullptr, nullptr, nullptr,
        (const float*)pq, (const float*)pk, (const int*)pknn,
        (bf16*)pa1h, (bf16*)pa1l);
    // h2 = relu(a1 @ gw1 + gb1) -> x1 (bf16 split)
    tgemm_bf<<<dim3(4, MROWS/128), 256, TG_SMEM>>>(
        (const bf16*)pa1h, (const bf16*)pa1l, nullptr,
        (const bf16*)pgw1h, (const bf16*)pgw1l, nullptr, nullptr,
        gb1, COUT, 1,
        nullptr, nullptr, (bf16*)px1h, (bf16*)px1l,
        nullptr, nullptr, nullptr, nullptr, nullptr);
    // att GEMM + fused softmax/weighted-sum -> r0 (bf16 split)
    tgemm_att<<<dim3(4, MROWS/128), 256, TG_SMEM>>>(
        (const bf16*)px1h, (const bf16*)px1l,
        (const bf16*)pgw2h, (const bf16*)pgw2l,
        gb2, COUT, (const int*)pknn,
        (const float*)ppos, (const float*)pv,
        (bf16*)pr0h, (bf16*)pr0l);
    // res1 = res0 @ lw + lb
    tgemm_bf<<<dim3(4, BSR/128), 256, TG_SMEM>>>(
        (const bf16*)pr0h, (const bf16*)pr0l, nullptr,
        (const bf16*)plwh, (const bf16*)plwl, nullptr, nullptr,
        lb, COUT, 0,
        (float*)pr1, nullptr, nullptr, nullptr,
        nullptr, nullptr, nullptr, nullptr, nullptr);
    // BatchNorm (training stats) + ReLU -> output
    bn_partial_kernel<<<64, 256>>>();
    bn_final_kernel<<<1, 256>>>(bng, bnb);
    bn_apply_kernel<<<(BSR*COUT)/1024, 1024>>>(res_out);
}

// round 10
// speedup vs baseline: 1.0724x; 1.0724x over previous
#include <cuda_runtime.h>
#include <cuda_bf16.h>
#include <math.h>
#include <stdint.h>

#define BB   8
#define NN   4096
#define SS   1024
#define KNBR 16
#define CIN  128
#define COUT 256
#define MROWS (BB*SS*KNBR)   /* 131072 */
#define BSR   (BB*SS)        /* 8192  */
#define NPTS  (BB*NN)        /* 32768 */

typedef __nv_bfloat16 bf16;

// ---------------- static device scratch (no allocs allowed) ----------------
__device__ float g_pos [(size_t)MROWS*COUT];
__device__ float g_att [(size_t)MROWS*COUT];
__device__ bf16  g_a1h [(size_t)MROWS*COUT];
__device__ bf16  g_a1l [(size_t)MROWS*COUT];
__device__ bf16  g_x1h [(size_t)MROWS*COUT];   // h1 then h2
__device__ bf16  g_x1l [(size_t)MROWS*COUT];
__device__ bf16  g_ph  [(size_t)NPTS*CIN];
__device__ bf16  g_pl  [(size_t)NPTS*CIN];
__device__ float g_kall[(size_t)NPTS*COUT];
__device__ float g_vall[(size_t)NPTS*COUT];
__device__ float g_q   [(size_t)BSR*COUT];
__device__ bf16  g_r0h [(size_t)BSR*COUT];
__device__ bf16  g_r0l [(size_t)BSR*COUT];
__device__ float g_res1[(size_t)BSR*COUT];
__device__ int   g_fps [BSR];
__device__ int   g_knn [MROWS];
__device__ float g_psum[64*COUT];
__device__ float g_psq [64*COUT];
__device__ float g_scale[COUT];
__device__ float g_shift[COUT];
// pre-split weights
__device__ bf16  g_wkh[CIN*COUT],  g_wkl[CIN*COUT];
__device__ bf16  g_wvh[CIN*COUT],  g_wvl[CIN*COUT];
__device__ bf16  g_wqh[CIN*COUT],  g_wql[CIN*COUT];
__device__ bf16  g_dw2h[COUT*COUT], g_dw2l[COUT*COUT];
__device__ bf16  g_gw1h[COUT*COUT], g_gw1l[COUT*COUT];
__device__ bf16  g_gw2h[COUT*COUT], g_gw2l[COUT*COUT];
__device__ bf16  g_lwh[COUT*COUT],  g_lwl[COUT*COUT];

// -------------------- bf16 split helper ------------------------------------
__device__ __forceinline__ void split2(float x0, float x1, uint32_t& hi, uint32_t& lo)
{
    bf16 h0 = __float2bfloat16(x0);
    bf16 h1 = __float2bfloat16(x1);
    float r0 = __fsub_rn(x0, __bfloat162float(h0));
    float r1 = __fsub_rn(x1, __bfloat162float(h1));
    bf16 l0 = __float2bfloat16(r0);
    bf16 l1 = __float2bfloat16(r1);
    hi = (uint32_t)__bfloat16_as_ushort(h0) | ((uint32_t)__bfloat16_as_ushort(h1) << 16);
    lo = (uint32_t)__bfloat16_as_ushort(l0) | ((uint32_t)__bfloat16_as_ushort(l1) << 16);
}

// -------------------- fp32 -> bf16 hi/lo conversion -------------------------
__device__ __forceinline__ void cvt_block(const float* __restrict__ src,
                                          bf16* __restrict__ hi, bf16* __restrict__ lo,
                                          int local_bid, int tid)
{
    int e = (local_bid * 256 + tid) * 2;
    uint32_t h, l;
    split2(src[e], src[e+1], h, l);
    *(uint32_t*)&hi[e] = h;
    *(uint32_t*)&lo[e] = l;
}

__global__ void cvt_kernel(const float* __restrict__ src,
                           bf16* __restrict__ hi, bf16* __restrict__ lo, int n)
{
    int e = (blockIdx.x * blockDim.x + threadIdx.x) * 2;
    if (e >= n) return;
    uint32_t h, l;
    split2(src[e], src[e+1], h, l);
    *(uint32_t*)&hi[e] = h;
    *(uint32_t*)&lo[e] = l;
}

// ------------------------- mma helpers --------------------------------------
__device__ __forceinline__ void cp16(void* s, const void* g)
{
    unsigned sa = (unsigned)__cvta_generic_to_shared(s);
    asm volatile("cp.async.ca.shared.global [%0], [%1], 16;\n" :: "r"(sa), "l"(g));
}
#define CP_COMMIT() asm volatile("cp.async.commit_group;\n")

__device__ __forceinline__ void ldsm_x4(uint32_t* r, const void* p)
{
    uint32_t a = (uint32_t)__cvta_generic_to_shared(p);
    asm volatile("ldmatrix.sync.aligned.m8n8.x4.shared.b16 {%0,%1,%2,%3}, [%4];"
                 : "=r"(r[0]), "=r"(r[1]), "=r"(r[2]), "=r"(r[3]) : "r"(a));
}

__device__ __forceinline__ void ldsm_x4_t(uint32_t* r, const void* p)
{
    uint32_t a = (uint32_t)__cvta_generic_to_shared(p);
    asm volatile("ldmatrix.sync.aligned.m8n8.x4.trans.shared.b16 {%0,%1,%2,%3}, [%4];"
                 : "=r"(r[0]), "=r"(r[1]), "=r"(r[2]), "=r"(r[3]) : "r"(a));
}

__device__ __forceinline__ void mma16816(float* c, const uint32_t* a, const uint32_t* b)
{
    asm volatile("mma.sync.aligned.m16n8k16.row.col.f32.bf16.bf16.f32 "
                 "{%0,%1,%2,%3}, {%4,%5,%6,%7}, {%8,%9}, {%0,%1,%2,%3};"
                 : "+f"(c[0]), "+f"(c[1]), "+f"(c[2]), "+f"(c[3])
                 : "r"(a[0]), "r"(a[1]), "r"(a[2]), "r"(a[3]),
                   "r"(b[0]), "r"(b[1]));
}

// ----------------------- shared GEMM mainloop macro -------------------------
#define KCH    16
#define NSTG   4
#define ASTR2  24
#define BSTR2  72
#define AS_BYTES  (NSTG*2*128*ASTR2*2)
#define BS_BYTES  (NSTG*2*KCH*BSTR2*2)
#define TG_SMEM   (AS_BYTES + BS_BYTES + 512)

#define GEMM_MAINLOOP(AHI, ALO, ROWMAP, WHI, WLO)                               \
    extern __shared__ char smraw[];                                            \
    typedef bf16 (*AsT)[2][128][ASTR2];                                        \
    typedef bf16 (*BsT)[2][KCH][BSTR2];                                        \
    AsT As = (AsT)smraw;                                                       \
    BsT Bs = (BsT)(smraw + AS_BYTES);                                          \
    int* rmap = (int*)(smraw + AS_BYTES + BS_BYTES);                           \
    if (tid < 128) rmap[tid] = (ROWMAP) ? (ROWMAP)[m0 + tid] : (m0 + tid);     \
    __syncthreads();                                                           \
    const int arow = tid >> 1;                                                 \
    const int ach  = (tid & 1) * 8;                                            \
    const bf16* aSrcH = (AHI) + (size_t)rmap[arow] * Kd + ach;                 \
    const bf16* aSrcL = (ALO) + (size_t)rmap[arow] * Kd + ach;                 \
    const int bpl = tid >> 7;                                                  \
    const int bk  = (tid >> 3) & 15;                                           \
    const int bch = (tid & 7) * 8;                                             \
    const bf16* bSrc = (bpl ? (WLO) : (WHI)) + (size_t)bk * COUT + n0 + bch;   \
    const int lane = tid & 31;                                                 \
    const int wm = (tid >> 5) >> 1;                                            \
    const int wn = (tid >> 5) & 1;                                             \
    const int aFrow = wm * 32 + (lane & 15);                                   \
    const int aFk   = (lane >> 4) * 8;                                         \
    const int bFk   = (lane & 7) + ((lane >> 3) & 1) * 8;                      \
    const int bFn   = (lane >> 4) * 8;                                         \
    float acc[2][4][4];                                                        \
    _Pragma("unroll")                                                          \
    for (int i = 0; i < 2; i++)                                                \
        _Pragma("unroll")                                                      \
        for (int j = 0; j < 4; j++)                                            \
            _Pragma("unroll")                                                  \
            for (int l = 0; l < 4; l++) acc[i][j][l] = 0.0f;                   \
    const int nk = Kd >> 4;                                                    \
    _Pragma("unroll")                                                          \
    for (int s = 0; s < NSTG - 1; s++) {                                       \
        if (s < nk) {                                                          \
            int k0 = s * KCH;                                                  \
            cp16(&As[s][0][arow][ach], aSrcH + k0);                            \
            cp16(&As[s][1][arow][ach], aSrcL + k0);                            \
            cp16(&Bs[s][bpl][bk][bch], bSrc + (size_t)k0 * COUT);              \
        }                                                                      \
        CP_COMMIT();                                                           \
    }                                                                          \
    for (int t = 0; t < nk; t++) {                                             \
        const int cur = t & (NSTG - 1);                                        \
        if (t + NSTG - 1 < nk) {                                               \
            asm volatile("cp.async.wait_group 2;\n" ::: "memory");             \
        } else {                                                               \
            asm volatile("cp.async.wait_group 0;\n" ::: "memory");             \
        }                                                                      \
        __syncthreads();                                                       \
        if (t + NSTG - 1 < nk) {                                               \
            const int stg = (t + NSTG - 1) & (NSTG - 1);                       \
            const int k0  = (t + NSTG - 1) * KCH;                              \
            cp16(&As[stg][0][arow][ach], aSrcH + k0);                          \
            cp16(&As[stg][1][arow][ach], aSrcL + k0);                          \
            cp16(&Bs[stg][bpl][bk][bch], bSrc + (size_t)k0 * COUT);            \
            CP_COMMIT();                                                       \
        }                                                                      \
        uint32_t ah[2][4], al[2][4], bh[4][2], bl[4][2];                       \
        _Pragma("unroll")                                                      \
        for (int mt = 0; mt < 2; mt++) {                                       \
            ldsm_x4(ah[mt], &As[cur][0][aFrow + mt*16][aFk]);                  \
            ldsm_x4(al[mt], &As[cur][1][aFrow + mt*16][aFk]);                  \
        }                                                                      \
        _Pragma("unroll")                                                      \
        for (int g = 0; g < 2; g++) {                                          \
            uint32_t tmp[4];                                                   \
            ldsm_x4_t(tmp, &Bs[cur][0][bFk][wn*32 + g*16 + bFn]);              \
            bh[g*2][0]   = tmp[0]; bh[g*2][1]   = tmp[1];                      \
            bh[g*2+1][0] = tmp[2]; bh[g*2+1][1] = tmp[3];                      \
            ldsm_x4_t(tmp, &Bs[cur][1][bFk][wn*32 + g*16 + bFn]);              \
            bl[g*2][0]   = tmp[0]; bl[g*2][1]   = tmp[1];                      \
            bl[g*2+1][0] = tmp[2]; bl[g*2+1][1] = tmp[3];                      \
        }                                                                      \
        _Pragma("unroll")                                                      \
        for (int mt = 0; mt < 2; mt++)                                         \
            _Pragma("unroll")                                                  \
            for (int nt = 0; nt < 4; nt++) {                                   \
                mma16816(acc[mt][nt], ah[mt], bh[nt]);                         \
                mma16816(acc[mt][nt], al[mt], bh[nt]);                         \
                mma16816(acc[mt][nt], ah[mt], bl[nt]);                         \
            }                                                                  \
    }

// ---------------- FUSED kernel: FPS (blocks 0-7) || kv GEMM || weight cvts --
#define KV_BLOCKS   (8 * (NPTS/128))          /* 2048 */
#define CVT_WQ_B    64
#define CVT_BIG_B   128
#define FUSED_GRID  (8 + KV_BLOCKS + CVT_WQ_B + 4*CVT_BIG_B)   /* 2632 */

__global__ __launch_bounds__(256, 2) void fused_fps_kv(
    const float* __restrict__ xyz, float* __restrict__ newxyz,
    const float* __restrict__ wq, const float* __restrict__ dw2,
    const float* __restrict__ gw1, const float* __restrict__ gw2,
    const float* __restrict__ lw)
{
    const int bid = blockIdx.x;
    const int tid = threadIdx.x;

    if (bid < 8) {
        // ------------------------- FPS -------------------------------------
        extern __shared__ char smtop[];
        float* sx = (float*)smtop;
        float* sy = sx + NN;
        float* sz = sy + NN;
        unsigned long long* swk = (unsigned long long*)(smtop + 3*NN*4); // [2][8]

        int b = bid;
        int lane = tid & 31, wid = tid >> 5;
        const float* base = xyz + (size_t)b * NN * 3;

        for (int i = tid; i < NN; i += 256) {
            sx[i] = base[i*3+0];
            sy[i] = base[i*3+1];
            sz[i] = base[i*3+2];
        }
        __syncthreads();

        float px[16], py[16], pz[16], dist[16];
#pragma unroll
        for (int j = 0; j < 16; j++) {
            int i = tid * 16 + j;
            px[j] = sx[i]; py[j] = sy[i]; pz[j] = sz[i];
            dist[j] = 1e10f;
        }

        int far = 0;
        for (int s = 0; s < SS; s++) {
            float cx = sx[far], cy = sy[far], cz = sz[far];
            if (tid == 0) {
                g_fps[b*SS + s] = b*NN + far;
                newxyz[((size_t)b*SS + s)*3 + 0] = cx;
                newxyz[((size_t)b*SS + s)*3 + 1] = cy;
                newxyz[((size_t)b*SS + s)*3 + 2] = cz;
            }
#pragma unroll
            for (int j = 0; j < 16; j++) {
                float dx = __fsub_rn(px[j], cx);
                float dy = __fsub_rn(py[j], cy);
                float dz = __fsub_rn(pz[j], cz);
                float d  = __fadd_rn(__fadd_rn(__fmul_rn(dx,dx), __fmul_rn(dy,dy)),
                                     __fmul_rn(dz,dz));
                dist[j] = fminf(dist[j], d);
            }
            // tree max over 16 (value only), then lowest-index match
            float m8[8];
#pragma unroll
            for (int j = 0; j < 8; j++) m8[j] = fmaxf(dist[j], dist[j+8]);
#pragma unroll
            for (int j = 0; j < 4; j++) m8[j] = fmaxf(m8[j], m8[j+4]);
            float bv = fmaxf(fmaxf(m8[0], m8[1]), fmaxf(m8[2], m8[3]));
            unsigned match = 0;
#pragma unroll
            for (int j = 0; j < 16; j++) match |= (dist[j] == bv) ? (1u << j) : 0u;
            int bi = tid*16 + (__ffs(match) - 1);

            unsigned key  = __float_as_uint(bv);
            unsigned wmax = __reduce_max_sync(0xffffffffu, key);
            unsigned ball = __ballot_sync(0xffffffffu, key == wmax);
            int src  = __ffs(ball) - 1;
            int wbi  = __shfl_sync(0xffffffffu, bi, src);
            if (lane == 0)
                swk[(s & 1)*8 + wid] = ((unsigned long long)wmax << 32)
                                     | (unsigned)(NN - 1 - wbi);
            __syncthreads();
            unsigned long long best = swk[(s & 1)*8 + 0];
#pragma unroll
            for (int w = 1; w < 8; w++) {
                unsigned long long c = swk[(s & 1)*8 + w];
                if (c > best) best = c;
            }
            far = NN - 1 - (int)(best & 0xffffffffu);
        }
        return;
    }

    if (bid < 8 + KV_BLOCKS) {
        // -------------------- merged k/v GEMM -------------------------------
        const int idx = bid - 8;
        const int bx  = idx & 7;           // 0..3 -> wk, 4..7 -> wv
        const int m0  = (idx >> 3) * 128;
        const int n0  = (bx & 3) * 64;
        const bf16* WhiS = (bx < 4) ? g_wkh : g_wvh;
        const bf16* WloS = (bx < 4) ? g_wkl : g_wvl;
        float* CS = (bx < 4) ? g_kall : g_vall;
        const int Kd = CIN;
        const int* rowmap = nullptr;

        GEMM_MAINLOOP(g_ph, g_pl, rowmap, WhiS, WloS)

        const int quad = lane >> 2, tq = lane & 3;
#pragma unroll
        for (int mt = 0; mt < 2; mt++) {
            int r0 = m0 + wm*32 + mt*16 + quad;
            int r1 = r0 + 8;
#pragma unroll
            for (int nt = 0; nt < 4; nt++) {
                int col = n0 + wn*32 + nt*8 + tq*2;
                *(float2*)(CS + (size_t)r0*COUT + col) =
                    make_float2(acc[mt][nt][0], acc[mt][nt][1]);
                *(float2*)(CS + (size_t)r1*COUT + col) =
                    make_float2(acc[mt][nt][2], acc[mt][nt][3]);
            }
        }
        return;
    }

    // ------------------------ weight conversions -----------------------------
    int cb = bid - (8 + KV_BLOCKS);
    if (cb < CVT_WQ_B) { cvt_block(wq, g_wqh, g_wql, cb, tid); return; }
    cb -= CVT_WQ_B;
    if (cb < CVT_BIG_B) { cvt_block(dw2, g_dw2h, g_dw2l, cb, tid); return; }
    cb -= CVT_BIG_B;
    if (cb < CVT_BIG_B) { cvt_block(gw1, g_gw1h, g_gw1l, cb, tid); return; }
    cb -= CVT_BIG_B;
    if (cb < CVT_BIG_B) { cvt_block(gw2, g_gw2h, g_gw2l, cb, tid); return; }
    cb -= CVT_BIG_B;
    cvt_block(lw, g_lwh, g_lwl, cb, tid);
}

// ---------------------------- KNN (R8 version: global reads) ----------------
__global__ __launch_bounds__(256) void knn_kernel(const float* __restrict__ xyz,
                                                  const float* __restrict__ newxyz)
{
    int warp = (blockIdx.x * blockDim.x + threadIdx.x) >> 5;
    int lane = threadIdx.x & 31;
    int wloc = threadIdx.x >> 5;
    int b = warp / SS;
    const float* base = xyz + (size_t)b * NN * 3;

    float nx = newxyz[(size_t)warp*3+0];
    float ny = newxyz[(size_t)warp*3+1];
    float nz = newxyz[(size_t)warp*3+2];
    float ns = fmaf(nz, nz, fmaf(ny, ny, __fmul_rn(nx, nx)));

    float v[16]; int id[16];
#pragma unroll
    for (int t = 0; t < 16; t++) { v[t] = 3.4e38f; id[t] = 0x7fffffff; }

    for (int j = lane; j < NN; j += 32) {
        float x = base[j*3+0], y = base[j*3+1], z = base[j*3+2];
        float dot = fmaf(z, nz, fmaf(y, ny, __fmul_rn(x, nx)));
        float nq  = fmaf(z, z,  fmaf(y, y,  __fmul_rn(x, x)));
        float d   = __fadd_rn(__fsub_rn(ns, __fmul_rn(2.0f, dot)), nq);
        if (d < v[15]) {
            v[15] = d; id[15] = j;
#pragma unroll
            for (int t = 15; t > 0; t--) {
                if (v[t] < v[t-1] || (v[t] == v[t-1] && id[t] < id[t-1])) {
                    float tv = v[t]; v[t] = v[t-1]; v[t-1] = tv;
                    int   ti = id[t]; id[t] = id[t-1]; id[t-1] = ti;
                } else break;
            }
        }
    }

    __shared__ float smd[8][512];
    __shared__ int   smi[8][512];
#pragma unroll
    for (int t = 0; t < 16; t++) {
        smd[wloc][lane*16 + t] = v[t];
        smi[wloc][lane*16 + t] = id[t];
    }
    __syncwarp();

    int p = 0;
    for (int t = 0; t < 16; t++) {
        float cv = (p < 16) ? smd[wloc][lane*16 + p] : 3.4e38f;
        int   ci = (p < 16) ? smi[wloc][lane*16 + p] : 0x7fffffff;
        float mv = cv; int mi = ci;
#pragma unroll
        for (int off = 16; off; off >>= 1) {
            float ov = __shfl_xor_sync(0xffffffffu, mv, off);
            int   oi = __shfl_xor_sync(0xffffffffu, mi, off);
            if (ov < mv || (ov == mv && oi < mi)) { mv = ov; mi = oi; }
        }
        if (cv == mv && ci == mi) p++;
        if (lane == 0) g_knn[(size_t)warp*16 + t] = b*NN + mi;
        __syncwarp();
    }
}

// --------- generic GEMM (fp32 out / bf16-split out / fused a1 dual write) ---
__global__ __launch_bounds__(256, 2) void tgemm_bf(
    const bf16* __restrict__ Ahi, const bf16* __restrict__ Alo,
    const int* __restrict__ rowmap,
    const bf16* __restrict__ Whi, const bf16* __restrict__ Wlo,
    const float* __restrict__ bias, int Kd, int relu,
    float* __restrict__ C, bf16* __restrict__ Chi, bf16* __restrict__ Clo,
    const float* __restrict__ qv, const float* __restrict__ kall,
    const int* __restrict__ knn,
    bf16* __restrict__ A1hi, bf16* __restrict__ A1lo)
{
    const int tid = threadIdx.x;
    const int m0  = blockIdx.y * 128;
    const int n0  = blockIdx.x * 64;

    GEMM_MAINLOOP(Ahi, Alo, rowmap, Whi, Wlo)

    const int quad = lane >> 2, tq = lane & 3;
#pragma unroll
    for (int mt = 0; mt < 2; mt++) {
        int r0 = m0 + wm*32 + mt*16 + quad;
        int r1 = r0 + 8;
        const float *q0 = nullptr, *k0p = nullptr, *q1 = nullptr, *k1p = nullptr;
        if (A1hi) {
            q0 = qv + (size_t)(r0 >> 4) * COUT;  k0p = kall + (size_t)knn[r0] * COUT;
            q1 = qv + (size_t)(r1 >> 4) * COUT;  k1p = kall + (size_t)knn[r1] * COUT;
        }
#pragma unroll
        for (int nt = 0; nt < 4; nt++) {
            int col = n0 + wn*32 + nt*8 + tq*2;
            float o0 = acc[mt][nt][0], o1 = acc[mt][nt][1];
            float o2 = acc[mt][nt][2], o3 = acc[mt][nt][3];
            if (bias) { float bb0 = bias[col], bb1 = bias[col+1];
                        o0 += bb0; o1 += bb1; o2 += bb0; o3 += bb1; }
            if (relu) { o0 = fmaxf(o0,0.f); o1 = fmaxf(o1,0.f);
                        o2 = fmaxf(o2,0.f); o3 = fmaxf(o3,0.f); }
            if (C) {
                *(float2*)(C + (size_t)r0*COUT + col) = make_float2(o0, o1);
                *(float2*)(C + (size_t)r1*COUT + col) = make_float2(o2, o3);
            }
            if (Chi) {
                uint32_t h, l;
                split2(o0, o1, h, l);
                *(uint32_t*)&Chi[(size_t)r0*COUT + col] = h;
                *(uint32_t*)&Clo[(size_t)r0*COUT + col] = l;
                split2(o2, o3, h, l);
                *(uint32_t*)&Chi[(size_t)r1*COUT + col] = h;
                *(uint32_t*)&Clo[(size_t)r1*COUT + col] = l;
            }
            if (A1hi) {
                float w0 = __fadd_rn(__fsub_rn(q0[col],   k0p[col]),   o0);
                float w1 = __fadd_rn(__fsub_rn(q0[col+1], k0p[col+1]), o1);
                float w2 = __fadd_rn(__fsub_rn(q1[col],   k1p[col]),   o2);
                float w3 = __fadd_rn(__fsub_rn(q1[col+1], k1p[col+1]), o3);
                uint32_t h, l;
                split2(w0, w1, h, l);
                *(uint32_t*)&A1hi[(size_t)r0*COUT + col] = h;
                *(uint32_t*)&A1lo[(size_t)r0*COUT + col] = l;
                split2(w2, w3, h, l);
                *(uint32_t*)&A1hi[(size_t)r1*COUT + col] = h;
                *(uint32_t*)&A1lo[(size_t)r1*COUT + col] = l;
            }
        }
    }
}

// ------------------ pos-enc layer 1 (3 -> 256, relu, bf16 split out) --------
__global__ void h1_kernel(const float* __restrict__ xyz, const float* __restrict__ newxyz,
                          const float* __restrict__ dw1, const float* __restrict__ db1)
{
    int r = blockIdx.x;
    int c = threadIdx.x * 2;
    int g  = g_knn[r];
    int bs = r >> 4;
    float cx = xyz[(size_t)g*3+0] - newxyz[(size_t)bs*3+0];
    float cy = xyz[(size_t)g*3+1] - newxyz[(size_t)bs*3+1];
    float cz = xyz[(size_t)g*3+2] - newxyz[(size_t)bs*3+2];
    float h0 = db1[c],   h1v = db1[c+1];
    h0  = fmaf(cx, dw1[0*COUT + c],   h0);
    h0  = fmaf(cy, dw1[1*COUT + c],   h0);
    h0  = fmaf(cz, dw1[2*COUT + c],   h0);
    h1v = fmaf(cx, dw1[0*COUT + c+1], h1v);
    h1v = fmaf(cy, dw1[1*COUT + c+1], h1v);
    h1v = fmaf(cz, dw1[2*COUT + c+1], h1v);
    h0  = fmaxf(h0, 0.0f);
    h1v = fmaxf(h1v, 0.0f);
    uint32_t h, l;
    split2(h0, h1v, h, l);
    *(uint32_t*)&g_x1h[(size_t)r*COUT + c] = h;
    *(uint32_t*)&g_x1l[(size_t)r*COUT + c] = l;
}

// --------------- softmax over K axis + weighted sum (v gathered) -----------
__global__ __launch_bounds__(128) void softmax_reduce_kernel()
{
    int bs = blockIdx.x;
    int c  = threadIdx.x * 2;
    __shared__ int kn[16];
    if (threadIdx.x < 16) kn[threadIdx.x] = g_knn[bs*16 + threadIdx.x];
    __syncthreads();

    size_t base = (size_t)bs * KNBR * COUT + c;
    float a0[16], a1[16];
    float mx0 = -3.4e38f, mx1 = -3.4e38f;
#pragma unroll
    for (int i = 0; i < 16; i++) {
        a0[i] = g_att[base + (size_t)i*COUT]     * 0.0625f;
        a1[i] = g_att[base + (size_t)i*COUT + 1] * 0.0625f;
        mx0 = fmaxf(mx0, a0[i]);
        mx1 = fmaxf(mx1, a1[i]);
    }
    float s0 = 0.0f, s1 = 0.0f;
#pragma unroll
    for (int i = 0; i < 16; i++) {
        a0[i] = expf(a0[i] - mx0); s0 += a0[i];
        a1[i] = expf(a1[i] - mx1); s1 += a1[i];
    }
    float i0 = 1.0f / s0, i1 = 1.0f / s1;
    float acc0 = 0.0f, acc1 = 0.0f;
#pragma unroll
    for (int i = 0; i < 16; i++) {
        size_t vb = (size_t)kn[i]*COUT + c;
        float vp0 = g_vall[vb]     + g_pos[base + (size_t)i*COUT];
        float vp1 = g_vall[vb + 1] + g_pos[base + (size_t)i*COUT + 1];
        acc0 = fmaf(a0[i]*i0, vp0, acc0);
        acc1 = fmaf(a1[i]*i1, vp1, acc1);
    }
    uint32_t h, l;
    split2(acc0, acc1, h, l);
    *(uint32_t*)&g_r0h[(size_t)bs*COUT + c] = h;
    *(uint32_t*)&g_r0l[(size_t)bs*COUT + c] = l;
}

// ---------------------------- BatchNorm ------------------------------------
__global__ void bn_partial_kernel()
{
    int blk = blockIdx.x;
    int c   = threadIdx.x;
    float s = 0.0f, q = 0.0f;
    for (int r = blk*128; r < blk*128 + 128; r++) {
        float x = g_res1[(size_t)r*COUT + c];
        s += x; q = fmaf(x, x, q);
    }
    g_psum[blk*COUT + c] = s;
    g_psq [blk*COUT + c] = q;
}

__global__ void bn_final_kernel(const float* __restrict__ bng, const float* __restrict__ bnb)
{
    int c = threadIdx.x;
    float s = 0.0f, q = 0.0f;
    for (int i = 0; i < 64; i++) { s += g_psum[i*COUT + c]; q += g_psq[i*COUT + c]; }
    float mean = s * (1.0f/(float)BSR);
    float var  = fmaxf(q * (1.0f/(float)BSR) - mean*mean, 0.0f);
    float sc   = bng[c] * rsqrtf(var + 1e-5f);
    g_scale[c] = sc;
    g_shift[c] = bnb[c] - mean * sc;
}

__global__ void bn_apply_kernel(float* __restrict__ out)
{
    size_t e = (size_t)blockIdx.x * blockDim.x + threadIdx.x;
    int c = (int)(e & 255);
    out[e] = fmaxf(fmaf(g_res1[e], g_scale[c], g_shift[c]), 0.0f);
}

// ------------------------------ launch --------------------------------------
extern "C" void kernel_launch(void* const* d_in, const int* in_sizes, int n_in,
                              void* d_out, int out_size)
{
    const float* xyz    = (const float*)d_in[0];
    const float* points = (const float*)d_in[1];
    const float* wq     = (const float*)d_in[2];
    const float* wk     = (const float*)d_in[3];
    const float* wv     = (const float*)d_in[4];
    const float* dw1    = (const float*)d_in[5];
    const float* db1    = (const float*)d_in[6];
    const float* dw2    = (const float*)d_in[7];
    const float* db2    = (const float*)d_in[8];
    const float* gw1    = (const float*)d_in[9];
    const float* gb1    = (const float*)d_in[10];
    const float* gw2    = (const float*)d_in[11];
    const float* gb2    = (const float*)d_in[12];
    const float* lw     = (const float*)d_in[13];
    const float* lb     = (const float*)d_in[14];
    const float* bng    = (const float*)d_in[15];
    const float* bnb    = (const float*)d_in[16];

    float* out     = (float*)d_out;
    float* newxyz  = out;
    float* res_out = out + (size_t)BSR*3;

    static bool attr_set = false;
    if (!attr_set) {
        cudaFuncSetAttribute(tgemm_bf,     cudaFuncAttributeMaxDynamicSharedMemorySize, TG_SMEM);
        cudaFuncSetAttribute(fused_fps_kv, cudaFuncAttributeMaxDynamicSharedMemorySize, TG_SMEM);
        attr_set = true;
    }

#define SYM(p, s) void* p; cudaGetSymbolAddress(&p, s)
    SYM(ppos, g_pos);  SYM(patt, g_att);
    SYM(pa1h, g_a1h);  SYM(pa1l, g_a1l);
    SYM(px1h, g_x1h);  SYM(px1l, g_x1l);
    SYM(pph,  g_ph);   SYM(ppl,  g_pl);
    SYM(pk,   g_kall); SYM(pv,   g_vall);
    SYM(pq,   g_q);
    SYM(pr0h, g_r0h);  SYM(pr0l, g_r0l);
    SYM(pr1,  g_res1);
    SYM(pfps, g_fps);  SYM(pknn, g_knn);
    SYM(pwkh, g_wkh);  SYM(pwkl, g_wkl);
    SYM(pwvh, g_wvh);  SYM(pwvl, g_wvl);
    SYM(pwqh, g_wqh);  SYM(pwql, g_wql);
    SYM(pdw2h, g_dw2h); SYM(pdw2l, g_dw2l);
    SYM(pgw1h, g_gw1h); SYM(pgw1l, g_gw1l);
    SYM(pgw2h, g_gw2h); SYM(pgw2l, g_gw2l);
    SYM(plwh, g_lwh);   SYM(plwl, g_lwl);
#undef SYM

    // 1-3: prerequisites of the fused kernel
    cvt_kernel<<<(NPTS*CIN)/512, 256>>>(points, (bf16*)pph, (bf16*)ppl, NPTS*CIN);
    cvt_kernel<<<(CIN*COUT)/512, 256>>>(wk, (bf16*)pwkh, (bf16*)pwkl, CIN*COUT);
    cvt_kernel<<<(CIN*COUT)/512, 256>>>(wv, (bf16*)pwvh, (bf16*)pwvl, CIN*COUT);
    // 4: FPS || merged k/v GEMM || remaining weight cvts
    fused_fps_kv<<<FUSED_GRID, 256, TG_SMEM>>>(xyz, newxyz, wq, dw2, gw1, gw2, lw);
    // 5: KNN
    knn_kernel<<<BSR/8, 256>>>(xyz, newxyz);
    // 6: q = gather(points, fps) @ wq
    tgemm_bf<<<dim3(4, BSR/128), 256, TG_SMEM>>>(
        (const bf16*)pph, (const bf16*)ppl, (const int*)pfps,
        (const bf16*)pwqh, (const bf16*)pwql, nullptr, CIN, 0,
        (float*)pq, nullptr, nullptr,
        nullptr, nullptr, nullptr, nullptr, nullptr);
    // 7: pos-enc layer 1 -> x1 (bf16 split)
    h1_kernel<<<MROWS, 128>>>(xyz, newxyz, dw1, db1);
    // 8: pos = h1 @ dw2 + db2 (fp32) + fused a1 = q - k_gather + pos (bf16 split)
    tgemm_bf<<<dim3(4, MROWS/128), 256, TG_SMEM>>>(
        (const bf16*)px1h, (const bf16*)px1l, nullptr,
        (const bf16*)pdw2h, (const bf16*)pdw2l, db2, COUT, 0,
        (float*)ppos, nullptr, nullptr,
        (const float*)pq, (const float*)pk, (const int*)pknn,
        (bf16*)pa1h, (bf16*)pa1l);
    // 9: h2 = relu(a1 @ gw1 + gb1) -> x1 (bf16 split)
    tgemm_bf<<<dim3(4, MROWS/128), 256, TG_SMEM>>>(
        (const bf16*)pa1h, (const bf16*)pa1l, nullptr,
        (const bf16*)pgw1h, (const bf16*)pgw1l, gb1, COUT, 1,
        nullptr, (bf16*)px1h, (bf16*)px1l,
        nullptr, nullptr, nullptr, nullptr, nullptr);
    // 10: att = h2 @ gw2 + gb2 -> fp32
    tgemm_bf<<<dim3(4, MROWS/128), 256, TG_SMEM>>>(
        (const bf16*)px1h, (const bf16*)px1l, nullptr,
        (const bf16*)pgw2h, (const bf16*)pgw2l, gb2, COUT, 0,
        (float*)patt, nullptr, nullptr,
        nullptr, nullptr, nullptr, nullptr, nullptr);
    // 11: softmax over K + weighted sum -> r0 (bf16 split)
    softmax_reduce_kernel<<<BSR, 128>>>();
    // 12: res1 = res0 @ lw + lb
    tgemm_bf<<<dim3(4, BSR/128), 256, TG_SMEM>>>(
        (const bf16*)pr0h, (const bf16*)pr0l, nullptr,
        (const bf16*)plwh, (const bf16*)plwl, lb, COUT, 0,
        (float*)pr1, nullptr, nullptr,
        nullptr, nullptr, nullptr, nullptr, nullptr);
    // 13: BatchNorm (training stats) + ReLU -> output
    bn_partial_kernel<<<64, 256>>>();
    bn_final_kernel<<<1, 256>>>(bng, bnb);
    bn_apply_kernel<<<(BSR*COUT)/1024, 1024>>>(res_out);
}

// round 11
// speedup vs baseline: 1.1584x; 1.0802x over previous
#include <cuda_runtime.h>
#include <cuda_bf16.h>
#include <math.h>
#include <stdint.h>

#define BB   8
#define NN   4096
#define SS   1024
#define KNBR 16
#define CIN  128
#define COUT 256
#define MROWS (BB*SS*KNBR)   /* 131072 */
#define BSR   (BB*SS)        /* 8192  */
#define NPTS  (BB*NN)        /* 32768 */

typedef __nv_bfloat16 bf16;

// ---------------- static device scratch (no allocs allowed) ----------------
__device__ float g_pos [(size_t)MROWS*COUT];
__device__ float g_att [(size_t)MROWS*COUT];
__device__ bf16  g_a1h [(size_t)MROWS*COUT];
__device__ bf16  g_a1l [(size_t)MROWS*COUT];
__device__ bf16  g_x1h [(size_t)MROWS*COUT];   // h1 then h2
__device__ bf16  g_x1l [(size_t)MROWS*COUT];
__device__ bf16  g_ph  [(size_t)NPTS*CIN];
__device__ bf16  g_pl  [(size_t)NPTS*CIN];
__device__ float g_kall[(size_t)NPTS*COUT];
__device__ float g_vall[(size_t)NPTS*COUT];
__device__ float g_q   [(size_t)BSR*COUT];
__device__ bf16  g_r0h [(size_t)BSR*COUT];
__device__ bf16  g_r0l [(size_t)BSR*COUT];
__device__ float g_res1[(size_t)BSR*COUT];
__device__ int   g_fps [BSR];
__device__ int   g_knn [MROWS];
__device__ int   g_prog[BB];
__device__ float g_psum[64*COUT];
__device__ float g_psq [64*COUT];
__device__ float g_scale[COUT];
__device__ float g_shift[COUT];
// pre-split weights
__device__ bf16  g_wkh[CIN*COUT],  g_wkl[CIN*COUT];
__device__ bf16  g_wvh[CIN*COUT],  g_wvl[CIN*COUT];
__device__ bf16  g_wqh[CIN*COUT],  g_wql[CIN*COUT];
__device__ bf16  g_dw2h[COUT*COUT], g_dw2l[COUT*COUT];
__device__ bf16  g_gw1h[COUT*COUT], g_gw1l[COUT*COUT];
__device__ bf16  g_gw2h[COUT*COUT], g_gw2l[COUT*COUT];
__device__ bf16  g_lwh[COUT*COUT],  g_lwl[COUT*COUT];

// -------------------- bf16 split helper ------------------------------------
__device__ __forceinline__ void split2(float x0, float x1, uint32_t& hi, uint32_t& lo)
{
    bf16 h0 = __float2bfloat16(x0);
    bf16 h1 = __float2bfloat16(x1);
    float r0 = __fsub_rn(x0, __bfloat162float(h0));
    float r1 = __fsub_rn(x1, __bfloat162float(h1));
    bf16 l0 = __float2bfloat16(r0);
    bf16 l1 = __float2bfloat16(r1);
    hi = (uint32_t)__bfloat16_as_ushort(h0) | ((uint32_t)__bfloat16_as_ushort(h1) << 16);
    lo = (uint32_t)__bfloat16_as_ushort(l0) | ((uint32_t)__bfloat16_as_ushort(l1) << 16);
}

__device__ __forceinline__ int ld_acquire(const int* p)
{
    int v;
    asm volatile("ld.acquire.gpu.global.b32 %0, [%1];" : "=r"(v) : "l"(p));
    return v;
}

// -------------------- fp32 -> bf16 hi/lo conversion -------------------------
__device__ __forceinline__ void cvt_block(const float* __restrict__ src,
                                          bf16* __restrict__ hi, bf16* __restrict__ lo,
                                          int local_bid, int tid)
{
    int e = (local_bid * 256 + tid) * 2;
    uint32_t h, l;
    split2(src[e], src[e+1], h, l);
    *(uint32_t*)&hi[e] = h;
    *(uint32_t*)&lo[e] = l;
}

__global__ void cvt_kernel(const float* __restrict__ src,
                           bf16* __restrict__ hi, bf16* __restrict__ lo, int n)
{
    int e = (blockIdx.x * blockDim.x + threadIdx.x) * 2;
    if (e >= n) return;
    uint32_t h, l;
    split2(src[e], src[e+1], h, l);
    *(uint32_t*)&hi[e] = h;
    *(uint32_t*)&lo[e] = l;
}

__global__ void reset_prog_kernel()
{
    if (threadIdx.x < BB) g_prog[threadIdx.x] = 0;
}

// ------------------------- mma helpers --------------------------------------
__device__ __forceinline__ void cp16(void* s, const void* g)
{
    unsigned sa = (unsigned)__cvta_generic_to_shared(s);
    asm volatile("cp.async.ca.shared.global [%0], [%1], 16;\n" :: "r"(sa), "l"(g));
}
#define CP_COMMIT() asm volatile("cp.async.commit_group;\n")

__device__ __forceinline__ void ldsm_x4(uint32_t* r, const void* p)
{
    uint32_t a = (uint32_t)__cvta_generic_to_shared(p);
    asm volatile("ldmatrix.sync.aligned.m8n8.x4.shared.b16 {%0,%1,%2,%3}, [%4];"
                 : "=r"(r[0]), "=r"(r[1]), "=r"(r[2]), "=r"(r[3]) : "r"(a));
}

__device__ __forceinline__ void ldsm_x4_t(uint32_t* r, const void* p)
{
    uint32_t a = (uint32_t)__cvta_generic_to_shared(p);
    asm volatile("ldmatrix.sync.aligned.m8n8.x4.trans.shared.b16 {%0,%1,%2,%3}, [%4];"
                 : "=r"(r[0]), "=r"(r[1]), "=r"(r[2]), "=r"(r[3]) : "r"(a));
}

__device__ __forceinline__ void mma16816(float* c, const uint32_t* a, const uint32_t* b)
{
    asm volatile("mma.sync.aligned.m16n8k16.row.col.f32.bf16.bf16.f32 "
                 "{%0,%1,%2,%3}, {%4,%5,%6,%7}, {%8,%9}, {%0,%1,%2,%3};"
                 : "+f"(c[0]), "+f"(c[1]), "+f"(c[2]), "+f"(c[3])
                 : "r"(a[0]), "r"(a[1]), "r"(a[2]), "r"(a[3]),
                   "r"(b[0]), "r"(b[1]));
}

// ----------------------- shared GEMM mainloop macro -------------------------
#define KCH    16
#define NSTG   4
#define ASTR2  24
#define BSTR2  72
#define AS_BYTES  (NSTG*2*128*ASTR2*2)
#define BS_BYTES  (NSTG*2*KCH*BSTR2*2)
#define TG_SMEM   (AS_BYTES + BS_BYTES + 512)

#define GEMM_MAINLOOP(AHI, ALO, ROWMAP, WHI, WLO)                               \
    extern __shared__ char smraw[];                                            \
    typedef bf16 (*AsT)[2][128][ASTR2];                                        \
    typedef bf16 (*BsT)[2][KCH][BSTR2];                                        \
    AsT As = (AsT)smraw;                                                       \
    BsT Bs = (BsT)(smraw + AS_BYTES);                                          \
    int* rmap = (int*)(smraw + AS_BYTES + BS_BYTES);                           \
    if (tid < 128) rmap[tid] = (ROWMAP) ? (ROWMAP)[m0 + tid] : (m0 + tid);     \
    __syncthreads();                                                           \
    const int arow = tid >> 1;                                                 \
    const int ach  = (tid & 1) * 8;                                            \
    const bf16* aSrcH = (AHI) + (size_t)rmap[arow] * Kd + ach;                 \
    const bf16* aSrcL = (ALO) + (size_t)rmap[arow] * Kd + ach;                 \
    const int bpl = tid >> 7;                                                  \
    const int bk  = (tid >> 3) & 15;                                           \
    const int bch = (tid & 7) * 8;                                             \
    const bf16* bSrc = (bpl ? (WLO) : (WHI)) + (size_t)bk * COUT + n0 + bch;   \
    const int lane = tid & 31;                                                 \
    const int wm = (tid >> 5) >> 1;                                            \
    const int wn = (tid >> 5) & 1;                                             \
    const int aFrow = wm * 32 + (lane & 15);                                   \
    const int aFk   = (lane >> 4) * 8;                                         \
    const int bFk   = (lane & 7) + ((lane >> 3) & 1) * 8;                      \
    const int bFn   = (lane >> 4) * 8;                                         \
    float acc[2][4][4];                                                        \
    _Pragma("unroll")                                                          \
    for (int i = 0; i < 2; i++)                                                \
        _Pragma("unroll")                                                      \
        for (int j = 0; j < 4; j++)                                            \
            _Pragma("unroll")                                                  \
            for (int l = 0; l < 4; l++) acc[i][j][l] = 0.0f;                   \
    const int nk = Kd >> 4;                                                    \
    _Pragma("unroll")                                                          \
    for (int s = 0; s < NSTG - 1; s++) {                                       \
        if (s < nk) {                                                          \
            int k0 = s * KCH;                                                  \
            cp16(&As[s][0][arow][ach], aSrcH + k0);                            \
            cp16(&As[s][1][arow][ach], aSrcL + k0);                            \
            cp16(&Bs[s][bpl][bk][bch], bSrc + (size_t)k0 * COUT);              \
        }                                                                      \
        CP_COMMIT();                                                           \
    }                                                                          \
    for (int t = 0; t < nk; t++) {                                             \
        const int cur = t & (NSTG - 1);                                        \
        if (t + NSTG - 1 < nk) {                                               \
            asm volatile("cp.async.wait_group 2;\n" ::: "memory");             \
        } else {                                                               \
            asm volatile("cp.async.wait_group 0;\n" ::: "memory");             \
        }                                                                      \
        __syncthreads();                                                       \
        if (t + NSTG - 1 < nk) {                                               \
            const int stg = (t + NSTG - 1) & (NSTG - 1);                       \
            const int k0  = (t + NSTG - 1) * KCH;                              \
            cp16(&As[stg][0][arow][ach], aSrcH + k0);                          \
            cp16(&As[stg][1][arow][ach], aSrcL + k0);                          \
            cp16(&Bs[stg][bpl][bk][bch], bSrc + (size_t)k0 * COUT);            \
            CP_COMMIT();                                                       \
        }                                                                      \
        uint32_t ah[2][4], al[2][4], bh[4][2], bl[4][2];                       \
        _Pragma("unroll")                                                      \
        for (int mt = 0; mt < 2; mt++) {                                       \
            ldsm_x4(ah[mt], &As[cur][0][aFrow + mt*16][aFk]);                  \
            ldsm_x4(al[mt], &As[cur][1][aFrow + mt*16][aFk]);                  \
        }                                                                      \
        _Pragma("unroll")                                                      \
        for (int g = 0; g < 2; g++) {                                          \
            uint32_t tmp[4];                                                   \
            ldsm_x4_t(tmp, &Bs[cur][0][bFk][wn*32 + g*16 + bFn]);              \
            bh[g*2][0]   = tmp[0]; bh[g*2][1]   = tmp[1];                      \
            bh[g*2+1][0] = tmp[2]; bh[g*2+1][1] = tmp[3];                      \
            ldsm_x4_t(tmp, &Bs[cur][1][bFk][wn*32 + g*16 + bFn]);              \
            bl[g*2][0]   = tmp[0]; bl[g*2][1]   = tmp[1];                      \
            bl[g*2+1][0] = tmp[2]; bl[g*2+1][1] = tmp[3];                      \
        }                                                                      \
        _Pragma("unroll")                                                      \
        for (int mt = 0; mt < 2; mt++)                                         \
            _Pragma("unroll")                                                  \
            for (int nt = 0; nt < 4; nt++) {                                   \
                mma16816(acc[mt][nt], ah[mt], bh[nt]);                         \
                mma16816(acc[mt][nt], al[mt], bh[nt]);                         \
                mma16816(acc[mt][nt], ah[mt], bl[nt]);                         \
            }                                                                  \
    }

// ------ FUSED kernel: FPS || kv GEMM || weight cvts || KNN (poll on FPS) ----
#define KV_BLOCKS   (8 * (NPTS/128))          /* 2048 */
#define CVT_WQ_B    64
#define CVT_BIG_B   128
#define CVT_TOTAL   (CVT_WQ_B + 4*CVT_BIG_B)  /* 576 */
#define KNN_BLOCKS  (BSR/8)                   /* 1024 */
#define FUSED_GRID  (8 + KV_BLOCKS + CVT_TOTAL + KNN_BLOCKS)

__global__ __launch_bounds__(256, 2) void fused_fps_kv(
    const float* __restrict__ xyz, float* __restrict__ newxyz,
    const float* __restrict__ wq, const float* __restrict__ dw2,
    const float* __restrict__ gw1, const float* __restrict__ gw2,
    const float* __restrict__ lw)
{
    const int bid = blockIdx.x;
    const int tid = threadIdx.x;

    if (bid < 8) {
        // ------------------------- FPS -------------------------------------
        extern __shared__ char smtop[];
        float* sx = (float*)smtop;
        float* sy = sx + NN;
        float* sz = sy + NN;
        unsigned long long* swk = (unsigned long long*)(smtop + 3*NN*4); // [2][8]

        int b = bid;
        int lane = tid & 31, wid = tid >> 5;
        const float* base = xyz + (size_t)b * NN * 3;

        for (int i = tid; i < NN; i += 256) {
            sx[i] = base[i*3+0];
            sy[i] = base[i*3+1];
            sz[i] = base[i*3+2];
        }
        __syncthreads();

        float px[16], py[16], pz[16], dist[16];
#pragma unroll
        for (int j = 0; j < 16; j++) {
            int i = tid * 16 + j;
            px[j] = sx[i]; py[j] = sy[i]; pz[j] = sz[i];
            dist[j] = 1e10f;
        }

        int far = 0;
        for (int s = 0; s < SS; s++) {
            float cx = sx[far], cy = sy[far], cz = sz[far];
            if (tid == 0) {
                g_fps[b*SS + s] = b*NN + far;
                newxyz[((size_t)b*SS + s)*3 + 0] = cx;
                newxyz[((size_t)b*SS + s)*3 + 1] = cy;
                newxyz[((size_t)b*SS + s)*3 + 2] = cz;
                if ((s & 31) == 31) {               // publish progress
                    __threadfence();
                    atomicExch(&g_prog[b], s + 1);
                }
            }
#pragma unroll
            for (int j = 0; j < 16; j++) {
                float dx = __fsub_rn(px[j], cx);
                float dy = __fsub_rn(py[j], cy);
                float dz = __fsub_rn(pz[j], cz);
                float d  = __fadd_rn(__fadd_rn(__fmul_rn(dx,dx), __fmul_rn(dy,dy)),
                                     __fmul_rn(dz,dz));
                dist[j] = fminf(dist[j], d);
            }
            float m8[8];
#pragma unroll
            for (int j = 0; j < 8; j++) m8[j] = fmaxf(dist[j], dist[j+8]);
#pragma unroll
            for (int j = 0; j < 4; j++) m8[j] = fmaxf(m8[j], m8[j+4]);
            float bv = fmaxf(fmaxf(m8[0], m8[1]), fmaxf(m8[2], m8[3]));
            unsigned match = 0;
#pragma unroll
            for (int j = 0; j < 16; j++) match |= (dist[j] == bv) ? (1u << j) : 0u;
            int bi = tid*16 + (__ffs(match) - 1);

            unsigned key  = __float_as_uint(bv);
            unsigned wmax = __reduce_max_sync(0xffffffffu, key);
            unsigned ball = __ballot_sync(0xffffffffu, key == wmax);
            int src  = __ffs(ball) - 1;
            int wbi  = __shfl_sync(0xffffffffu, bi, src);
            if (lane == 0)
                swk[(s & 1)*8 + wid] = ((unsigned long long)wmax << 32)
                                     | (unsigned)(NN - 1 - wbi);
            __syncthreads();
            unsigned long long best = swk[(s & 1)*8 + 0];
#pragma unroll
            for (int w = 1; w < 8; w++) {
                unsigned long long c = swk[(s & 1)*8 + w];
                if (c > best) best = c;
            }
            far = NN - 1 - (int)(best & 0xffffffffu);
        }
        return;
    }

    if (bid < 8 + KV_BLOCKS) {
        // -------------------- merged k/v GEMM -------------------------------
        const int idx = bid - 8;
        const int bx  = idx & 7;           // 0..3 -> wk, 4..7 -> wv
        const int m0  = (idx >> 3) * 128;
        const int n0  = (bx & 3) * 64;
        const bf16* WhiS = (bx < 4) ? g_wkh : g_wvh;
        const bf16* WloS = (bx < 4) ? g_wkl : g_wvl;
        float* CS = (bx < 4) ? g_kall : g_vall;
        const int Kd = CIN;
        const int* rowmap = nullptr;

        GEMM_MAINLOOP(g_ph, g_pl, rowmap, WhiS, WloS)

        const int quad = lane >> 2, tq = lane & 3;
#pragma unroll
        for (int mt = 0; mt < 2; mt++) {
            int r0 = m0 + wm*32 + mt*16 + quad;
            int r1 = r0 + 8;
#pragma unroll
            for (int nt = 0; nt < 4; nt++) {
                int col = n0 + wn*32 + nt*8 + tq*2;
                *(float2*)(CS + (size_t)r0*COUT + col) =
                    make_float2(acc[mt][nt][0], acc[mt][nt][1]);
                *(float2*)(CS + (size_t)r1*COUT + col) =
                    make_float2(acc[mt][nt][2], acc[mt][nt][3]);
            }
        }
        return;
    }

    if (bid < 8 + KV_BLOCKS + CVT_TOTAL) {
        // ------------------------ weight conversions ------------------------
        int cb = bid - (8 + KV_BLOCKS);
        if (cb < CVT_WQ_B) { cvt_block(wq, g_wqh, g_wql, cb, tid); return; }
        cb -= CVT_WQ_B;
        if (cb < CVT_BIG_B) { cvt_block(dw2, g_dw2h, g_dw2l, cb, tid); return; }
        cb -= CVT_BIG_B;
        if (cb < CVT_BIG_B) { cvt_block(gw1, g_gw1h, g_gw1l, cb, tid); return; }
        cb -= CVT_BIG_B;
        if (cb < CVT_BIG_B) { cvt_block(gw2, g_gw2h, g_gw2l, cb, tid); return; }
        cb -= CVT_BIG_B;
        cvt_block(lw, g_lwh, g_lwl, cb, tid);
        return;
    }

    // ------------------------- KNN (polls FPS progress) ---------------------
    {
        extern __shared__ char smk[];
        float (*smd)[512] = (float(*)[512])smk;            // 8*512*4 = 16 KB
        int   (*smi)[512] = (int(*)[512])(smk + 8*512*4);  // 16 KB

        const int kb   = bid - (8 + KV_BLOCKS + CVT_TOTAL);
        const int lane = tid & 31;
        const int wloc = tid >> 5;
        const int b    = kb & 7;                    // round-robin batches
        const int s    = (kb >> 3) * 8 + wloc;      // sample within batch
        const int warp = b * SS + s;
        const float* base = xyz + (size_t)b * NN * 3;

        if (lane == 0) {
            while (ld_acquire(&g_prog[b]) <= s) { }
        }
        __syncwarp();

        float nx = __ldcg(newxyz + (size_t)warp*3 + 0);
        float ny = __ldcg(newxyz + (size_t)warp*3 + 1);
        float nz = __ldcg(newxyz + (size_t)warp*3 + 2);
        float ns = fmaf(nz, nz, fmaf(ny, ny, __fmul_rn(nx, nx)));

        float v[16]; int id[16];
#pragma unroll
        for (int t = 0; t < 16; t++) { v[t] = 3.4e38f; id[t] = 0x7fffffff; }

        for (int j = lane; j < NN; j += 32) {
            float x = base[j*3+0], y = base[j*3+1], z = base[j*3+2];
            float dot = fmaf(z, nz, fmaf(y, ny, __fmul_rn(x, nx)));
            float nq  = fmaf(z, z,  fmaf(y, y,  __fmul_rn(x, x)));
            float d   = __fadd_rn(__fsub_rn(ns, __fmul_rn(2.0f, dot)), nq);
            if (d < v[15]) {
                v[15] = d; id[15] = j;
#pragma unroll
                for (int t = 15; t > 0; t--) {
                    if (v[t] < v[t-1] || (v[t] == v[t-1] && id[t] < id[t-1])) {
                        float tv = v[t]; v[t] = v[t-1]; v[t-1] = tv;
                        int   ti = id[t]; id[t] = id[t-1]; id[t-1] = ti;
                    } else break;
                }
            }
        }

#pragma unroll
        for (int t = 0; t < 16; t++) {
            smd[wloc][lane*16 + t] = v[t];
            smi[wloc][lane*16 + t] = id[t];
        }
        __syncwarp();

        int p = 0;
        for (int t = 0; t < 16; t++) {
            float cv = (p < 16) ? smd[wloc][lane*16 + p] : 3.4e38f;
            int   ci = (p < 16) ? smi[wloc][lane*16 + p] : 0x7fffffff;
            float mv = cv; int mi = ci;
#pragma unroll
            for (int off = 16; off; off >>= 1) {
                float ov = __shfl_xor_sync(0xffffffffu, mv, off);
                int   oi = __shfl_xor_sync(0xffffffffu, mi, off);
                if (ov < mv || (ov == mv && oi < mi)) { mv = ov; mi = oi; }
            }
            if (cv == mv && ci == mi) p++;
            if (lane == 0) g_knn[(size_t)warp*16 + t] = b*NN + mi;
            __syncwarp();
        }
    }
}

// --------- generic GEMM (fp32 out / bf16-split out / fused a1 dual write) ---
__global__ __launch_bounds__(256, 2) void tgemm_bf(
    const bf16* __restrict__ Ahi, const bf16* __restrict__ Alo,
    const int* __restrict__ rowmap,
    const bf16* __restrict__ Whi, const bf16* __restrict__ Wlo,
    const float* __restrict__ bias, int Kd, int relu,
    float* __restrict__ C, bf16* __restrict__ Chi, bf16* __restrict__ Clo,
    const float* __restrict__ qv, const float* __restrict__ kall,
    const int* __restrict__ knn,
    bf16* __restrict__ A1hi, bf16* __restrict__ A1lo)
{
    const int tid = threadIdx.x;
    const int m0  = blockIdx.y * 128;
    const int n0  = blockIdx.x * 64;

    GEMM_MAINLOOP(Ahi, Alo, rowmap, Whi, Wlo)

    const int quad = lane >> 2, tq = lane & 3;
#pragma unroll
    for (int mt = 0; mt < 2; mt++) {
        int r0 = m0 + wm*32 + mt*16 + quad;
        int r1 = r0 + 8;
        const float *q0 = nullptr, *k0p = nullptr, *q1 = nullptr, *k1p = nullptr;
        if (A1hi) {
            q0 = qv + (size_t)(r0 >> 4) * COUT;  k0p = kall + (size_t)knn[r0] * COUT;
            q1 = qv + (size_t)(r1 >> 4) * COUT;  k1p = kall + (size_t)knn[r1] * COUT;
        }
#pragma unroll
        for (int nt = 0; nt < 4; nt++) {
            int col = n0 + wn*32 + nt*8 + tq*2;
            float o0 = acc[mt][nt][0], o1 = acc[mt][nt][1];
            float o2 = acc[mt][nt][2], o3 = acc[mt][nt][3];
            if (bias) { float bb0 = bias[col], bb1 = bias[col+1];
                        o0 += bb0; o1 += bb1; o2 += bb0; o3 += bb1; }
            if (relu) { o0 = fmaxf(o0,0.f); o1 = fmaxf(o1,0.f);
                        o2 = fmaxf(o2,0.f); o3 = fmaxf(o3,0.f); }
            if (C) {
                *(float2*)(C + (size_t)r0*COUT + col) = make_float2(o0, o1);
                *(float2*)(C + (size_t)r1*COUT + col) = make_float2(o2, o3);
            }
            if (Chi) {
                uint32_t h, l;
                split2(o0, o1, h, l);
                *(uint32_t*)&Chi[(size_t)r0*COUT + col] = h;
                *(uint32_t*)&Clo[(size_t)r0*COUT + col] = l;
                split2(o2, o3, h, l);
                *(uint32_t*)&Chi[(size_t)r1*COUT + col] = h;
                *(uint32_t*)&Clo[(size_t)r1*COUT + col] = l;
            }
            if (A1hi) {
                float w0 = __fadd_rn(__fsub_rn(q0[col],   k0p[col]),   o0);
                float w1 = __fadd_rn(__fsub_rn(q0[col+1], k0p[col+1]), o1);
                float w2 = __fadd_rn(__fsub_rn(q1[col],   k1p[col]),   o2);
                float w3 = __fadd_rn(__fsub_rn(q1[col+1], k1p[col+1]), o3);
                uint32_t h, l;
                split2(w0, w1, h, l);
                *(uint32_t*)&A1hi[(size_t)r0*COUT + col] = h;
                *(uint32_t*)&A1lo[(size_t)r0*COUT + col] = l;
                split2(w2, w3, h, l);
                *(uint32_t*)&A1hi[(size_t)r1*COUT + col] = h;
                *(uint32_t*)&A1lo[(size_t)r1*COUT + col] = l;
            }
        }
    }
}

// ------------------ pos-enc layer 1 (3 -> 256, relu, bf16 split out) --------
__global__ void h1_kernel(const float* __restrict__ xyz, const float* __restrict__ newxyz,
                          const float* __restrict__ dw1, const float* __restrict__ db1)
{
    int r = blockIdx.x;
    int c = threadIdx.x * 2;
    int g  = g_knn[r];
    int bs = r >> 4;
    float cx = xyz[(size_t)g*3+0] - newxyz[(size_t)bs*3+0];
    float cy = xyz[(size_t)g*3+1] - newxyz[(size_t)bs*3+1];
    float cz = xyz[(size_t)g*3+2] - newxyz[(size_t)bs*3+2];
    float h0 = db1[c],   h1v = db1[c+1];
    h0  = fmaf(cx, dw1[0*COUT + c],   h0);
    h0  = fmaf(cy, dw1[1*COUT + c],   h0);
    h0  = fmaf(cz, dw1[2*COUT + c],   h0);
    h1v = fmaf(cx, dw1[0*COUT + c+1], h1v);
    h1v = fmaf(cy, dw1[1*COUT + c+1], h1v);
    h1v = fmaf(cz, dw1[2*COUT + c+1], h1v);
    h0  = fmaxf(h0, 0.0f);
    h1v = fmaxf(h1v, 0.0f);
    uint32_t h, l;
    split2(h0, h1v, h, l);
    *(uint32_t*)&g_x1h[(size_t)r*COUT + c] = h;
    *(uint32_t*)&g_x1l[(size_t)r*COUT + c] = l;
}

// --------------- softmax over K axis + weighted sum (v gathered) -----------
__global__ __launch_bounds__(128) void softmax_reduce_kernel()
{
    int bs = blockIdx.x;
    int c  = threadIdx.x * 2;
    __shared__ int kn[16];
    if (threadIdx.x < 16) kn[threadIdx.x] = g_knn[bs*16 + threadIdx.x];
    __syncthreads();

    size_t base = (size_t)bs * KNBR * COUT + c;
    float a0[16], a1[16];
    float mx0 = -3.4e38f, mx1 = -3.4e38f;
#pragma unroll
    for (int i = 0; i < 16; i++) {
        a0[i] = g_att[base + (size_t)i*COUT]     * 0.0625f;
        a1[i] = g_att[base + (size_t)i*COUT + 1] * 0.0625f;
        mx0 = fmaxf(mx0, a0[i]);
        mx1 = fmaxf(mx1, a1[i]);
    }
    float s0 = 0.0f, s1 = 0.0f;
#pragma unroll
    for (int i = 0; i < 16; i++) {
        a0[i] = expf(a0[i] - mx0); s0 += a0[i];
        a1[i] = expf(a1[i] - mx1); s1 += a1[i];
    }
    float i0 = 1.0f / s0, i1 = 1.0f / s1;
    float acc0 = 0.0f, acc1 = 0.0f;
#pragma unroll
    for (int i = 0; i < 16; i++) {
        size_t vb = (size_t)kn[i]*COUT + c;
        float vp0 = g_vall[vb]     + g_pos[base + (size_t)i*COUT];
        float vp1 = g_vall[vb + 1] + g_pos[base + (size_t)i*COUT + 1];
        acc0 = fmaf(a0[i]*i0, vp0, acc0);
        acc1 = fmaf(a1[i]*i1, vp1, acc1);
    }
    uint32_t h, l;
    split2(acc0, acc1, h, l);
    *(uint32_t*)&g_r0h[(size_t)bs*COUT + c] = h;
    *(uint32_t*)&g_r0l[(size_t)bs*COUT + c] = l;
}

// ---------------------------- BatchNorm ------------------------------------
__global__ void bn_partial_kernel()
{
    int blk = blockIdx.x;
    int c   = threadIdx.x;
    float s = 0.0f, q = 0.0f;
    for (int r = blk*128; r < blk*128 + 128; r++) {
        float x = g_res1[(size_t)r*COUT + c];
        s += x; q = fmaf(x, x, q);
    }
    g_psum[blk*COUT + c] = s;
    g_psq [blk*COUT + c] = q;
}

__global__ void bn_final_kernel(const float* __restrict__ bng, const float* __restrict__ bnb)
{
    int c = threadIdx.x;
    float s = 0.0f, q = 0.0f;
    for (int i = 0; i < 64; i++) { s += g_psum[i*COUT + c]; q += g_psq[i*COUT + c]; }
    float mean = s * (1.0f/(float)BSR);
    float var  = fmaxf(q * (1.0f/(float)BSR) - mean*mean, 0.0f);
    float sc   = bng[c] * rsqrtf(var + 1e-5f);
    g_scale[c] = sc;
    g_shift[c] = bnb[c] - mean * sc;
}

__global__ void bn_apply_kernel(float* __restrict__ out)
{
    size_t e = (size_t)blockIdx.x * blockDim.x + threadIdx.x;
    int c = (int)(e & 255);
    out[e] = fmaxf(fmaf(g_res1[e], g_scale[c], g_shift[c]), 0.0f);
}

// ------------------------------ launch --------------------------------------
extern "C" void kernel_launch(void* const* d_in, const int* in_sizes, int n_in,
                              void* d_out, int out_size)
{
    const float* xyz    = (const float*)d_in[0];
    const float* points = (const float*)d_in[1];
    const float* wq     = (const float*)d_in[2];
    const float* wk     = (const float*)d_in[3];
    const float* wv     = (const float*)d_in[4];
    const float* dw1    = (const float*)d_in[5];
    const float* db1    = (const float*)d_in[6];
    const float* dw2    = (const float*)d_in[7];
    const float* db2    = (const float*)d_in[8];
    const float* gw1    = (const float*)d_in[9];
    const float* gb1    = (const float*)d_in[10];
    const float* gw2    = (const float*)d_in[11];
    const float* gb2    = (const float*)d_in[12];
    const float* lw     = (const float*)d_in[13];
    const float* lb     = (const float*)d_in[14];
    const float* bng    = (const float*)d_in[15];
    const float* bnb    = (const float*)d_in[16];

    float* out     = (float*)d_out;
    float* newxyz  = out;
    float* res_out = out + (size_t)BSR*3;

    static bool attr_set = false;
    if (!attr_set) {
        cudaFuncSetAttribute(tgemm_bf,     cudaFuncAttributeMaxDynamicSharedMemorySize, TG_SMEM);
        cudaFuncSetAttribute(fused_fps_kv, cudaFuncAttributeMaxDynamicSharedMemorySize, TG_SMEM);
        attr_set = true;
    }

#define SYM(p, s) void* p; cudaGetSymbolAddress(&p, s)
    SYM(ppos, g_pos);  SYM(patt, g_att);
    SYM(pa1h, g_a1h);  SYM(pa1l, g_a1l);
    SYM(px1h, g_x1h);  SYM(px1l, g_x1l);
    SYM(pph,  g_ph);   SYM(ppl,  g_pl);
    SYM(pk,   g_kall); SYM(pv,   g_vall);
    SYM(pq,   g_q);
    SYM(pr0h, g_r0h);  SYM(pr0l, g_r0l);
    SYM(pr1,  g_res1);
    SYM(pfps, g_fps);  SYM(pknn, g_knn);
    SYM(pwqh, g_wqh);  SYM(pwql, g_wql);
    SYM(pwkh, g_wkh);  SYM(pwkl, g_wkl);
    SYM(pwvh, g_wvh);  SYM(pwvl, g_wvl);
    SYM(pdw2h, g_dw2h); SYM(pdw2l, g_dw2l);
    SYM(pgw1h, g_gw1h); SYM(pgw1l, g_gw1l);
    SYM(pgw2h, g_gw2h); SYM(pgw2l, g_gw2l);
    SYM(plwh, g_lwh);   SYM(plwl, g_lwl);
#undef SYM

    // 1: reset progress counters (graph-replay safe)
    reset_prog_kernel<<<1, 32>>>();
    // 2-4: prerequisites of the fused kernel
    cvt_kernel<<<(NPTS*CIN)/512, 256>>>(points, (bf16*)pph, (bf16*)ppl, NPTS*CIN);
    cvt_kernel<<<(CIN*COUT)/512, 256>>>(wk, (bf16*)pwkh, (bf16*)pwkl, CIN*COUT);
    cvt_kernel<<<(CIN*COUT)/512, 256>>>(wv, (bf16*)pwvh, (bf16*)pwvl, CIN*COUT);
    // 5: FPS || merged k/v GEMM || weight cvts || KNN (polling)
    fused_fps_kv<<<FUSED_GRID, 256, TG_SMEM>>>(xyz, newxyz, wq, dw2, gw1, gw2, lw);
    // 6: q = gather(points, fps) @ wq
    tgemm_bf<<<dim3(4, BSR/128), 256, TG_SMEM>>>(
        (const bf16*)pph, (const bf16*)ppl, (const int*)pfps,
        (const bf16*)pwqh, (const bf16*)pwql, nullptr, CIN, 0,
        (float*)pq, nullptr, nullptr,
        nullptr, nullptr, nullptr, nullptr, nullptr);
    // 7: pos-enc layer 1 -> x1 (bf16 split)
    h1_kernel<<<MROWS, 128>>>(xyz, newxyz, dw1, db1);
    // 8: pos = h1 @ dw2 + db2 (fp32) + fused a1 = q - k_gather + pos (bf16 split)
    tgemm_bf<<<dim3(4, MROWS/128), 256, TG_SMEM>>>(
        (const bf16*)px1h, (const bf16*)px1l, nullptr,
        (const bf16*)pdw2h, (const bf16*)pdw2l, db2, COUT, 0,
        (float*)ppos, nullptr, nullptr,
        (const float*)pq, (const float*)pk, (const int*)pknn,
        (bf16*)pa1h, (bf16*)pa1l);
    // 9: h2 = relu(a1 @ gw1 + gb1) -> x1 (bf16 split)
    tgemm_bf<<<dim3(4, MROWS/128), 256, TG_SMEM>>>(
        (const bf16*)pa1h, (const bf16*)pa1l, nullptr,
        (const bf16*)pgw1h, (const bf16*)pgw1l, gb1, COUT, 1,
        nullptr, (bf16*)px1h, (bf16*)px1l,
        nullptr, nullptr, nullptr, nullptr, nullptr);
    // 10: att = h2 @ gw2 + gb2 -> fp32
    tgemm_bf<<<dim3(4, MROWS/128), 256, TG_SMEM>>>(
        (const bf16*)px1h, (const bf16*)px1l, nullptr,
        (const bf16*)pgw2h, (const bf16*)pgw2l, gb2, COUT, 0,
        (float*)patt, nullptr, nullptr,
        nullptr, nullptr, nullptr, nullptr, nullptr);
    // 11: softmax over K + weighted sum -> r0 (bf16 split)
    softmax_reduce_kernel<<<BSR, 128>>>();
    // 12: res1 = res0 @ lw + lb
    tgemm_bf<<<dim3(4, BSR/128), 256, TG_SMEM>>>(
        (const bf16*)pr0h, (const bf16*)pr0l, nullptr,
        (const bf16*)plwh, (const bf16*)plwl, lb, COUT, 0,
        (float*)pr1, nullptr, nullptr,
        nullptr, nullptr, nullptr, nullptr, nullptr);
    // 13: BatchNorm (training stats) + ReLU -> output
    bn_partial_kernel<<<64, 256>>>();
    bn_final_kernel<<<1, 256>>>(bng, bnb);
    bn_apply_kernel<<<(BSR*COUT)/1024, 1024>>>(res_out);
}

// round 12
// speedup vs baseline: 1.2017x; 1.0374x over previous
#include <cuda_runtime.h>
#include <cuda_bf16.h>
#include <math.h>
#include <stdint.h>

#define BB   8
#define NN   4096
#define SS   1024
#define KNBR 16
#define CIN  128
#define COUT 256
#define MROWS (BB*SS*KNBR)   /* 131072 */
#define BSR   (BB*SS)        /* 8192  */
#define NPTS  (BB*NN)        /* 32768 */

typedef __nv_bfloat16 bf16;

// ---------------- static device scratch (no allocs allowed) ----------------
__device__ float g_pos [(size_t)MROWS*COUT];
__device__ float g_att [(size_t)MROWS*COUT];
__device__ bf16  g_a1h [(size_t)MROWS*COUT];
__device__ bf16  g_a1l [(size_t)MROWS*COUT];
__device__ bf16  g_x1h [(size_t)MROWS*COUT];   // h1 then h2
__device__ bf16  g_x1l [(size_t)MROWS*COUT];
__device__ bf16  g_ph  [(size_t)NPTS*CIN];
__device__ bf16  g_pl  [(size_t)NPTS*CIN];
__device__ float g_kall[(size_t)NPTS*COUT];
__device__ float g_vall[(size_t)NPTS*COUT];
__device__ float g_q   [(size_t)BSR*COUT];
__device__ bf16  g_r0h [(size_t)BSR*COUT];
__device__ bf16  g_r0l [(size_t)BSR*COUT];
__device__ float g_res1[(size_t)BSR*COUT];
__device__ int   g_fps [BSR];
__device__ int   g_knn [MROWS];
__device__ int   g_prog[BB];
__device__ int   g_kprog[BB];
__device__ int   g_cvtcnt;
__device__ float g_psum[64*COUT];
__device__ float g_psq [64*COUT];
__device__ float g_scale[COUT];
__device__ float g_shift[COUT];
// pre-split weights
__device__ bf16  g_wkh[CIN*COUT],  g_wkl[CIN*COUT];
__device__ bf16  g_wvh[CIN*COUT],  g_wvl[CIN*COUT];
__device__ bf16  g_wqh[CIN*COUT],  g_wql[CIN*COUT];
__device__ bf16  g_dw2h[COUT*COUT], g_dw2l[COUT*COUT];
__device__ bf16  g_gw1h[COUT*COUT], g_gw1l[COUT*COUT];
__device__ bf16  g_gw2h[COUT*COUT], g_gw2l[COUT*COUT];
__device__ bf16  g_lwh[COUT*COUT],  g_lwl[COUT*COUT];

// -------------------- bf16 split helper ------------------------------------
__device__ __forceinline__ void split2(float x0, float x1, uint32_t& hi, uint32_t& lo)
{
    bf16 h0 = __float2bfloat16(x0);
    bf16 h1 = __float2bfloat16(x1);
    float r0 = __fsub_rn(x0, __bfloat162float(h0));
    float r1 = __fsub_rn(x1, __bfloat162float(h1));
    bf16 l0 = __float2bfloat16(r0);
    bf16 l1 = __float2bfloat16(r1);
    hi = (uint32_t)__bfloat16_as_ushort(h0) | ((uint32_t)__bfloat16_as_ushort(h1) << 16);
    lo = (uint32_t)__bfloat16_as_ushort(l0) | ((uint32_t)__bfloat16_as_ushort(l1) << 16);
}

__device__ __forceinline__ int ld_acquire(const int* p)
{
    int v;
    asm volatile("ld.acquire.gpu.global.b32 %0, [%1];" : "=r"(v) : "l"(p));
    return v;
}

// ---------------- wide fp32 -> bf16 hi/lo conversion (8 elems/thread) -------
__device__ __forceinline__ void cvt_block_wide(const float* __restrict__ src,
                                               bf16* __restrict__ hi, bf16* __restrict__ lo,
                                               int local_bid, int tid)
{
    int e = (local_bid * 256 + tid) * 8;
    float4 a = *(const float4*)(src + e);
    float4 c = *(const float4*)(src + e + 4);
    uint32_t h0,l0,h1,l1,h2,l2,h3,l3;
    split2(a.x, a.y, h0, l0); split2(a.z, a.w, h1, l1);
    split2(c.x, c.y, h2, l2); split2(c.z, c.w, h3, l3);
    uint4 H; H.x = h0; H.y = h1; H.z = h2; H.w = h3;
    uint4 L; L.x = l0; L.y = l1; L.z = l2; L.w = l3;
    *(uint4*)&hi[e] = H;
    *(uint4*)&lo[e] = L;
}

__global__ void reset_prog_kernel()
{
    int t = threadIdx.x;
    if (t < BB) g_prog[t] = 0;
    if (t >= 32 && t < 32 + BB) g_kprog[t - 32] = 0;
    if (t == 63) g_cvtcnt = 0;
}

// ------------------------- mma helpers --------------------------------------
__device__ __forceinline__ void cp16(void* s, const void* g)
{
    unsigned sa = (unsigned)__cvta_generic_to_shared(s);
    asm volatile("cp.async.ca.shared.global [%0], [%1], 16;\n" :: "r"(sa), "l"(g));
}
#define CP_COMMIT() asm volatile("cp.async.commit_group;\n")

__device__ __forceinline__ void ldsm_x4(uint32_t* r, const void* p)
{
    uint32_t a = (uint32_t)__cvta_generic_to_shared(p);
    asm volatile("ldmatrix.sync.aligned.m8n8.x4.shared.b16 {%0,%1,%2,%3}, [%4];"
                 : "=r"(r[0]), "=r"(r[1]), "=r"(r[2]), "=r"(r[3]) : "r"(a));
}

__device__ __forceinline__ void ldsm_x4_t(uint32_t* r, const void* p)
{
    uint32_t a = (uint32_t)__cvta_generic_to_shared(p);
    asm volatile("ldmatrix.sync.aligned.m8n8.x4.trans.shared.b16 {%0,%1,%2,%3}, [%4];"
                 : "=r"(r[0]), "=r"(r[1]), "=r"(r[2]), "=r"(r[3]) : "r"(a));
}

__device__ __forceinline__ void mma16816(float* c, const uint32_t* a, const uint32_t* b)
{
    asm volatile("mma.sync.aligned.m16n8k16.row.col.f32.bf16.bf16.f32 "
                 "{%0,%1,%2,%3}, {%4,%5,%6,%7}, {%8,%9}, {%0,%1,%2,%3};"
                 : "+f"(c[0]), "+f"(c[1]), "+f"(c[2]), "+f"(c[3])
                 : "r"(a[0]), "r"(a[1]), "r"(a[2]), "r"(a[3]),
                   "r"(b[0]), "r"(b[1]));
}

// ----------------------- shared GEMM mainloop macro -------------------------
#define KCH    16
#define NSTG   4
#define ASTR2  24
#define BSTR2  72
#define AS_BYTES  (NSTG*2*128*ASTR2*2)
#define BS_BYTES  (NSTG*2*KCH*BSTR2*2)
#define TG_SMEM   (AS_BYTES + BS_BYTES + 512)

#define GEMM_MAINLOOP(AHI, ALO, ROWMAP, WHI, WLO)                               \
    extern __shared__ char smraw[];                                            \
    typedef bf16 (*AsT)[2][128][ASTR2];                                        \
    typedef bf16 (*BsT)[2][KCH][BSTR2];                                        \
    AsT As = (AsT)smraw;                                                       \
    BsT Bs = (BsT)(smraw + AS_BYTES);                                          \
    int* rmap = (int*)(smraw + AS_BYTES + BS_BYTES);                           \
    if (tid < 128) rmap[tid] = (ROWMAP) ? __ldcg((ROWMAP) + m0 + tid) : (m0 + tid); \
    __syncthreads();                                                           \
    const int arow = tid >> 1;                                                 \
    const int ach  = (tid & 1) * 8;                                            \
    const bf16* aSrcH = (AHI) + (size_t)rmap[arow] * Kd + ach;                 \
    const bf16* aSrcL = (ALO) + (size_t)rmap[arow] * Kd + ach;                 \
    const int bpl = tid >> 7;                                                  \
    const int bk  = (tid >> 3) & 15;                                           \
    const int bch = (tid & 7) * 8;                                             \
    const bf16* bSrc = (bpl ? (WLO) : (WHI)) + (size_t)bk * COUT + n0 + bch;   \
    const int lane = tid & 31;                                                 \
    const int wm = (tid >> 5) >> 1;                                            \
    const int wn = (tid >> 5) & 1;                                             \
    const int aFrow = wm * 32 + (lane & 15);                                   \
    const int aFk   = (lane >> 4) * 8;                                         \
    const int bFk   = (lane & 7) + ((lane >> 3) & 1) * 8;                      \
    const int bFn   = (lane >> 4) * 8;                                         \
    float acc[2][4][4];                                                        \
    _Pragma("unroll")                                                          \
    for (int i = 0; i < 2; i++)                                                \
        _Pragma("unroll")                                                      \
        for (int j = 0; j < 4; j++)                                            \
            _Pragma("unroll")                                                  \
            for (int l = 0; l < 4; l++) acc[i][j][l] = 0.0f;                   \
    const int nk = Kd >> 4;                                                    \
    _Pragma("unroll")                                                          \
    for (int s = 0; s < NSTG - 1; s++) {                                       \
        if (s < nk) {                                                          \
            int k0 = s * KCH;                                                  \
            cp16(&As[s][0][arow][ach], aSrcH + k0);                            \
            cp16(&As[s][1][arow][ach], aSrcL + k0);                            \
            cp16(&Bs[s][bpl][bk][bch], bSrc + (size_t)k0 * COUT);              \
        }                                                                      \
        CP_COMMIT();                                                           \
    }                                                                          \
    for (int t = 0; t < nk; t++) {                                             \
        const int cur = t & (NSTG - 1);                                        \
        if (t + NSTG - 1 < nk) {                                               \
            asm volatile("cp.async.wait_group 2;\n" ::: "memory");             \
        } else {                                                               \
            asm volatile("cp.async.wait_group 0;\n" ::: "memory");             \
        }                                                                      \
        __syncthreads();                                                       \
        if (t + NSTG - 1 < nk) {                                               \
            const int stg = (t + NSTG - 1) & (NSTG - 1);                       \
            const int k0  = (t + NSTG - 1) * KCH;                              \
            cp16(&As[stg][0][arow][ach], aSrcH + k0);                          \
            cp16(&As[stg][1][arow][ach], aSrcL + k0);                          \
            cp16(&Bs[stg][bpl][bk][bch], bSrc + (size_t)k0 * COUT);            \
            CP_COMMIT();                                                       \
        }                                                                      \
        uint32_t ah[2][4], al[2][4], bh[4][2], bl[4][2];                       \
        _Pragma("unroll")                                                      \
        for (int mt = 0; mt < 2; mt++) {                                       \
            ldsm_x4(ah[mt], &As[cur][0][aFrow + mt*16][aFk]);                  \
            ldsm_x4(al[mt], &As[cur][1][aFrow + mt*16][aFk]);                  \
        }                                                                      \
        _Pragma("unroll")                                                      \
        for (int g = 0; g < 2; g++) {                                          \
            uint32_t tmp[4];                                                   \
            ldsm_x4_t(tmp, &Bs[cur][0][bFk][wn*32 + g*16 + bFn]);              \
            bh[g*2][0]   = tmp[0]; bh[g*2][1]   = tmp[1];                      \
            bh[g*2+1][0] = tmp[2]; bh[g*2+1][1] = tmp[3];                      \
            ldsm_x4_t(tmp, &Bs[cur][1][bFk][wn*32 + g*16 + bFn]);              \
            bl[g*2][0]   = tmp[0]; bl[g*2][1]   = tmp[1];                      \
            bl[g*2+1][0] = tmp[2]; bl[g*2+1][1] = tmp[3];                      \
        }                                                                      \
        _Pragma("unroll")                                                      \
        for (int mt = 0; mt < 2; mt++)                                         \
            _Pragma("unroll")                                                  \
            for (int nt = 0; nt < 4; nt++) {                                   \
                mma16816(acc[mt][nt], ah[mt], bh[nt]);                         \
                mma16816(acc[mt][nt], al[mt], bh[nt]);                         \
                mma16816(acc[mt][nt], ah[mt], bl[nt]);                         \
            }                                                                  \
    }

// ------ FUSED kernel block ranges -------------------------------------------
#define CVT_PTS_B    (NPTS*CIN/2048)          /* 2048 */
#define CVT_WSM_B    (CIN*COUT/2048)          /* 16   */
#define CVT_WBG_B    (COUT*COUT/2048)         /* 32   */
#define CVT_PRE_TOT  (CVT_PTS_B + 2*CVT_WSM_B)            /* 2080 */
#define KV_BLOCKS    (8 * (NPTS/128))                     /* 2048 */
#define CVT_POST_TOT (CVT_WSM_B + 4*CVT_WBG_B)            /* 144  */
#define KNN_BLOCKS   (BSR/8)                              /* 1024 */
#define Q_BLOCKS     (4 * (BSR/128))                      /* 256  */
#define H1_BLOCKS    (MROWS/128)                          /* 1024 */

#define B_CVTPRE   8
#define B_KV       (B_CVTPRE + CVT_PRE_TOT)
#define B_CVTPOST  (B_KV + KV_BLOCKS)
#define B_KNN      (B_CVTPOST + CVT_POST_TOT)
#define B_Q        (B_KNN + KNN_BLOCKS)
#define B_H1       (B_Q + Q_BLOCKS)
#define FUSED_GRID (B_H1 + H1_BLOCKS)

__global__ __launch_bounds__(256, 2) void fused_all(
    const float* __restrict__ xyz, float* __restrict__ newxyz,
    const float* __restrict__ points,
    const float* __restrict__ wk, const float* __restrict__ wv,
    const float* __restrict__ wq, const float* __restrict__ dw2,
    const float* __restrict__ gw1, const float* __restrict__ gw2,
    const float* __restrict__ lw,
    const float* __restrict__ dw1, const float* __restrict__ db1)
{
    const int bid = blockIdx.x;
    const int tid = threadIdx.x;

    if (bid < 8) {
        // ------------------------- FPS -------------------------------------
        extern __shared__ char smtop[];
        float* sx = (float*)smtop;
        float* sy = sx + NN;
        float* sz = sy + NN;
        unsigned long long* swk = (unsigned long long*)(smtop + 3*NN*4); // [2][8]

        int b = bid;
        int lane = tid & 31, wid = tid >> 5;
        const float* base = xyz + (size_t)b * NN * 3;

        for (int i = tid; i < NN; i += 256) {
            sx[i] = base[i*3+0];
            sy[i] = base[i*3+1];
            sz[i] = base[i*3+2];
        }
        __syncthreads();

        float px[16], py[16], pz[16], dist[16];
#pragma unroll
        for (int j = 0; j < 16; j++) {
            int i = tid * 16 + j;
            px[j] = sx[i]; py[j] = sy[i]; pz[j] = sz[i];
            dist[j] = 1e10f;
        }

        int far = 0;
        for (int s = 0; s < SS; s++) {
            float cx = sx[far], cy = sy[far], cz = sz[far];
            if (tid == 0) {
                g_fps[b*SS + s] = b*NN + far;
                newxyz[((size_t)b*SS + s)*3 + 0] = cx;
                newxyz[((size_t)b*SS + s)*3 + 1] = cy;
                newxyz[((size_t)b*SS + s)*3 + 2] = cz;
                if ((s & 31) == 31) {
                    __threadfence();
                    atomicExch(&g_prog[b], s + 1);
                }
            }
#pragma unroll
            for (int j = 0; j < 16; j++) {
                float dx = __fsub_rn(px[j], cx);
                float dy = __fsub_rn(py[j], cy);
                float dz = __fsub_rn(pz[j], cz);
                float d  = __fadd_rn(__fadd_rn(__fmul_rn(dx,dx), __fmul_rn(dy,dy)),
                                     __fmul_rn(dz,dz));
                dist[j] = fminf(dist[j], d);
            }
            float m8[8];
#pragma unroll
            for (int j = 0; j < 8; j++) m8[j] = fmaxf(dist[j], dist[j+8]);
#pragma unroll
            for (int j = 0; j < 4; j++) m8[j] = fmaxf(m8[j], m8[j+4]);
            float bv = fmaxf(fmaxf(m8[0], m8[1]), fmaxf(m8[2], m8[3]));
            unsigned match = 0;
#pragma unroll
            for (int j = 0; j < 16; j++) match |= (dist[j] == bv) ? (1u << j) : 0u;
            int bi = tid*16 + (__ffs(match) - 1);

            unsigned key  = __float_as_uint(bv);
            unsigned wmax = __reduce_max_sync(0xffffffffu, key);
            unsigned ball = __ballot_sync(0xffffffffu, key == wmax);
            int src  = __ffs(ball) - 1;
            int wbi  = __shfl_sync(0xffffffffu, bi, src);
            if (lane == 0)
                swk[(s & 1)*8 + wid] = ((unsigned long long)wmax << 32)
                                     | (unsigned)(NN - 1 - wbi);
            __syncthreads();
            unsigned long long best = swk[(s & 1)*8 + 0];
#pragma unroll
            for (int w = 1; w < 8; w++) {
                unsigned long long c = swk[(s & 1)*8 + w];
                if (c > best) best = c;
            }
            far = NN - 1 - (int)(best & 0xffffffffu);
        }
        return;
    }

    if (bid < B_KV) {
        // ------------- pre-cvts (points, wk, wv) + release counter ----------
        int cb = bid - B_CVTPRE;
        if (cb < CVT_PTS_B)               cvt_block_wide(points, g_ph, g_pl, cb, tid);
        else if (cb < CVT_PTS_B + CVT_WSM_B)
            cvt_block_wide(wk, g_wkh, g_wkl, cb - CVT_PTS_B, tid);
        else
            cvt_block_wide(wv, g_wvh, g_wvl, cb - CVT_PTS_B - CVT_WSM_B, tid);
        __syncthreads();
        if (tid == 0) { __threadfence(); atomicAdd(&g_cvtcnt, 1); }
        return;
    }

    if (bid < B_CVTPOST) {
        // -------------------- merged k/v GEMM (polls cvtcnt) ----------------
        if (tid == 0) { while (ld_acquire(&g_cvtcnt) < CVT_PRE_TOT) { } }
        const int idx = bid - B_KV;
        const int bx  = idx & 7;           // 0..3 -> wk, 4..7 -> wv
        const int m0  = (idx >> 3) * 128;
        const int n0  = (bx & 3) * 64;
        const bf16* WhiS = (bx < 4) ? g_wkh : g_wvh;
        const bf16* WloS = (bx < 4) ? g_wkl : g_wvl;
        float* CS = (bx < 4) ? g_kall : g_vall;
        const int Kd = CIN;
        const int* rowmap = nullptr;

        GEMM_MAINLOOP(g_ph, g_pl, rowmap, WhiS, WloS)

        const int quad = lane >> 2, tq = lane & 3;
#pragma unroll
        for (int mt = 0; mt < 2; mt++) {
            int r0 = m0 + wm*32 + mt*16 + quad;
            int r1 = r0 + 8;
#pragma unroll
            for (int nt = 0; nt < 4; nt++) {
                int col = n0 + wn*32 + nt*8 + tq*2;
                *(float2*)(CS + (size_t)r0*COUT + col) =
                    make_float2(acc[mt][nt][0], acc[mt][nt][1]);
                *(float2*)(CS + (size_t)r1*COUT + col) =
                    make_float2(acc[mt][nt][2], acc[mt][nt][3]);
            }
        }
        return;
    }

    if (bid < B_KNN) {
        // ------------------------ post weight cvts ---------------------------
        int cb = bid - B_CVTPOST;
        if (cb < CVT_WSM_B) { cvt_block_wide(wq, g_wqh, g_wql, cb, tid); return; }
        cb -= CVT_WSM_B;
        if (cb < CVT_WBG_B) { cvt_block_wide(dw2, g_dw2h, g_dw2l, cb, tid); return; }
        cb -= CVT_WBG_B;
        if (cb < CVT_WBG_B) { cvt_block_wide(gw1, g_gw1h, g_gw1l, cb, tid); return; }
        cb -= CVT_WBG_B;
        if (cb < CVT_WBG_B) { cvt_block_wide(gw2, g_gw2h, g_gw2l, cb, tid); return; }
        cb -= CVT_WBG_B;
        cvt_block_wide(lw, g_lwh, g_lwl, cb, tid);
        return;
    }

    if (bid < B_Q) {
        // ------------- KNN (polls FPS progress, commits kprog) ---------------
        extern __shared__ char smk[];
        float (*smd)[512] = (float(*)[512])smk;
        int   (*smi)[512] = (int(*)[512])(smk + 8*512*4);

        const int kb   = bid - B_KNN;
        const int lane = tid & 31;
        const int wloc = tid >> 5;
        const int b    = kb & 7;
        const int s0   = (kb >> 3) * 8;
        const int s    = s0 + wloc;
        const int warp = b * SS + s;
        const float* base = xyz + (size_t)b * NN * 3;

        if (lane == 0) {
            while (ld_acquire(&g_prog[b]) <= s) { }
        }
        __syncwarp();

        float nx = __ldcg(newxyz + (size_t)warp*3 + 0);
        float ny = __ldcg(newxyz + (size_t)warp*3 + 1);
        float nz = __ldcg(newxyz + (size_t)warp*3 + 2);
        float ns = fmaf(nz, nz, fmaf(ny, ny, __fmul_rn(nx, nx)));

        float v[16]; int id[16];
#pragma unroll
        for (int t = 0; t < 16; t++) { v[t] = 3.4e38f; id[t] = 0x7fffffff; }

        for (int j = lane; j < NN; j += 32) {
            float x = base[j*3+0], y = base[j*3+1], z = base[j*3+2];
            float dot = fmaf(z, nz, fmaf(y, ny, __fmul_rn(x, nx)));
            float nq  = fmaf(z, z,  fmaf(y, y,  __fmul_rn(x, x)));
            float d   = __fadd_rn(__fsub_rn(ns, __fmul_rn(2.0f, dot)), nq);
            if (d < v[15]) {
                v[15] = d; id[15] = j;
#pragma unroll
                for (int t = 15; t > 0; t--) {
                    if (v[t] < v[t-1] || (v[t] == v[t-1] && id[t] < id[t-1])) {
                        float tv = v[t]; v[t] = v[t-1]; v[t-1] = tv;
                        int   ti = id[t]; id[t] = id[t-1]; id[t-1] = ti;
                    } else break;
                }
            }
        }

#pragma unroll
        for (int t = 0; t < 16; t++) {
            smd[wloc][lane*16 + t] = v[t];
            smi[wloc][lane*16 + t] = id[t];
        }
        __syncwarp();

        int p = 0;
        for (int t = 0; t < 16; t++) {
            float cv = (p < 16) ? smd[wloc][lane*16 + p] : 3.4e38f;
            int   ci = (p < 16) ? smi[wloc][lane*16 + p] : 0x7fffffff;
            float mv = cv; int mi = ci;
#pragma unroll
            for (int off = 16; off; off >>= 1) {
                float ov = __shfl_xor_sync(0xffffffffu, mv, off);
                int   oi = __shfl_xor_sync(0xffffffffu, mi, off);
                if (ov < mv || (ov == mv && oi < mi)) { mv = ov; mi = oi; }
            }
            if (cv == mv && ci == mi) p++;
            if (lane == 0) g_knn[(size_t)warp*16 + t] = b*NN + mi;
            __syncwarp();
        }

        // in-order commit of per-batch KNN progress
        __syncthreads();
        if (tid == 0) {
            while (ld_acquire(&g_kprog[b]) != s0) { }
            __threadfence();
            atomicExch(&g_kprog[b], s0 + 8);
        }
        return;
    }

    if (bid < B_H1) {
        // -------------- q GEMM = gather(points, fps) @ wq (polls prog) -------
        const int idx = bid - B_Q;
        const int n0  = (idx & 3) * 64;
        const int m0  = (idx >> 2) * 128;
        const int b   = m0 >> 10;
        const int s_need = (m0 & 1023) + 128;
        if (tid == 0) { while (ld_acquire(&g_prog[b]) < s_need) { } }
        const int Kd = CIN;
        const int* fps_ptr = g_fps;

        GEMM_MAINLOOP(g_ph, g_pl, fps_ptr, g_wqh, g_wql)

        const int quad = lane >> 2, tq = lane & 3;
#pragma unroll
        for (int mt = 0; mt < 2; mt++) {
            int r0 = m0 + wm*32 + mt*16 + quad;
            int r1 = r0 + 8;
#pragma unroll
            for (int nt = 0; nt < 4; nt++) {
                int col = n0 + wn*32 + nt*8 + tq*2;
                *(float2*)(g_q + (size_t)r0*COUT + col) =
                    make_float2(acc[mt][nt][0], acc[mt][nt][1]);
                *(float2*)(g_q + (size_t)r1*COUT + col) =
                    make_float2(acc[mt][nt][2], acc[mt][nt][3]);
            }
        }
        return;
    }

    // ----------------- h1 pos-enc layer 1 (polls kprog) ----------------------
    {
        const int hb = bid - B_H1;           // 0..1023, rows [hb*128, +128)
        const int b  = hb >> 7;
        const int s_need = ((hb * 8) & 1023) + 8;
        if (tid == 0) { while (ld_acquire(&g_kprog[b]) < s_need) { } }
        __syncthreads();

        const int col    = (tid & 127) * 2;
        const int rowsel = tid >> 7;
        const float w0a = dw1[col],        w0b = dw1[col+1];
        const float w1a = dw1[COUT+col],   w1b = dw1[COUT+col+1];
        const float w2a = dw1[2*COUT+col], w2b = dw1[2*COUT+col+1];
        const float b0  = db1[col],        b1  = db1[col+1];

        for (int rr = 0; rr < 64; rr++) {
            int r  = hb*128 + rr*2 + rowsel;
            int g  = __ldcg(&g_knn[r]);
            int bs = r >> 4;
            float cx = __ldcg(&xyz[(size_t)g*3+0]) - __ldcg(&newxyz[(size_t)bs*3+0]);
            float cy = __ldcg(&xyz[(size_t)g*3+1]) - __ldcg(&newxyz[(size_t)bs*3+1]);
            float cz = __ldcg(&xyz[(size_t)g*3+2]) - __ldcg(&newxyz[(size_t)bs*3+2]);
            float h0 = b0, h1v = b1;
            h0  = fmaf(cx, w0a, h0);  h0  = fmaf(cy, w1a, h0);  h0  = fmaf(cz, w2a, h0);
            h1v = fmaf(cx, w0b, h1v); h1v = fmaf(cy, w1b, h1v); h1v = fmaf(cz, w2b, h1v);
            h0  = fmaxf(h0, 0.0f);
            h1v = fmaxf(h1v, 0.0f);
            uint32_t h, l;
            split2(h0, h1v, h, l);
            *(uint32_t*)&g_x1h[(size_t)r*COUT + col] = h;
            *(uint32_t*)&g_x1l[(size_t)r*COUT + col] = l;
        }
    }
}

// --------- generic GEMM (fp32 out / bf16-split out / fused a1 dual write) ---
__global__ __launch_bounds__(256, 2) void tgemm_bf(
    const bf16* __restrict__ Ahi, const bf16* __restrict__ Alo,
    const int* __restrict__ rowmap,
    const bf16* __restrict__ Whi, const bf16* __restrict__ Wlo,
    const float* __restrict__ bias, int Kd, int relu,
    float* __restrict__ C, bf16* __restrict__ Chi, bf16* __restrict__ Clo,
    const float* __restrict__ qv, const float* __restrict__ kall,
    const int* __restrict__ knn,
    bf16* __restrict__ A1hi, bf16* __restrict__ A1lo)
{
    const int tid = threadIdx.x;
    const int m0  = blockIdx.y * 128;
    const int n0  = blockIdx.x * 64;

    GEMM_MAINLOOP(Ahi, Alo, rowmap, Whi, Wlo)

    const int quad = lane >> 2, tq = lane & 3;
#pragma unroll
    for (int mt = 0; mt < 2; mt++) {
        int r0 = m0 + wm*32 + mt*16 + quad;
        int r1 = r0 + 8;
        const float *q0 = nullptr, *k0p = nullptr, *q1 = nullptr, *k1p = nullptr;
        if (A1hi) {
            q0 = qv + (size_t)(r0 >> 4) * COUT;  k0p = kall + (size_t)knn[r0] * COUT;
            q1 = qv + (size_t)(r1 >> 4) * COUT;  k1p = kall + (size_t)knn[r1] * COUT;
        }
#pragma unroll
        for (int nt = 0; nt < 4; nt++) {
            int col = n0 + wn*32 + nt*8 + tq*2;
            float o0 = acc[mt][nt][0], o1 = acc[mt][nt][1];
            float o2 = acc[mt][nt][2], o3 = acc[mt][nt][3];
            if (bias) { float bb0 = bias[col], bb1 = bias[col+1];
                        o0 += bb0; o1 += bb1; o2 += bb0; o3 += bb1; }
            if (relu) { o0 = fmaxf(o0,0.f); o1 = fmaxf(o1,0.f);
                        o2 = fmaxf(o2,0.f); o3 = fmaxf(o3,0.f); }
            if (C) {
                *(float2*)(C + (size_t)r0*COUT + col) = make_float2(o0, o1);
                *(float2*)(C + (size_t)r1*COUT + col) = make_float2(o2, o3);
            }
            if (Chi) {
                uint32_t h, l;
                split2(o0, o1, h, l);
                *(uint32_t*)&Chi[(size_t)r0*COUT + col] = h;
                *(uint32_t*)&Clo[(size_t)r0*COUT + col] = l;
                split2(o2, o3, h, l);
                *(uint32_t*)&Chi[(size_t)r1*COUT + col] = h;
                *(uint32_t*)&Clo[(size_t)r1*COUT + col] = l;
            }
            if (A1hi) {
                float w0 = __fadd_rn(__fsub_rn(q0[col],   k0p[col]),   o0);
                float w1 = __fadd_rn(__fsub_rn(q0[col+1], k0p[col+1]), o1);
                float w2 = __fadd_rn(__fsub_rn(q1[col],   k1p[col]),   o2);
                float w3 = __fadd_rn(__fsub_rn(q1[col+1], k1p[col+1]), o3);
                uint32_t h, l;
                split2(w0, w1, h, l);
                *(uint32_t*)&A1hi[(size_t)r0*COUT + col] = h;
                *(uint32_t*)&A1lo[(size_t)r0*COUT + col] = l;
                split2(w2, w3, h, l);
                *(uint32_t*)&A1hi[(size_t)r1*COUT + col] = h;
                *(uint32_t*)&A1lo[(size_t)r1*COUT + col] = l;
            }
        }
    }
}

// --------------- softmax over K axis + weighted sum (v gathered) -----------
__global__ __launch_bounds__(128) void softmax_reduce_kernel()
{
    int bs = blockIdx.x;
    int c  = threadIdx.x * 2;
    __shared__ int kn[16];
    if (threadIdx.x < 16) kn[threadIdx.x] = g_knn[bs*16 + threadIdx.x];
    __syncthreads();

    size_t base = (size_t)bs * KNBR * COUT + c;
    float a0[16], a1[16];
    float mx0 = -3.4e38f, mx1 = -3.4e38f;
#pragma unroll
    for (int i = 0; i < 16; i++) {
        a0[i] = g_att[base + (size_t)i*COUT]     * 0.0625f;
        a1[i] = g_att[base + (size_t)i*COUT + 1] * 0.0625f;
        mx0 = fmaxf(mx0, a0[i]);
        mx1 = fmaxf(mx1, a1[i]);
    }
    float s0 = 0.0f, s1 = 0.0f;
#pragma unroll
    for (int i = 0; i < 16; i++) {
        a0[i] = expf(a0[i] - mx0); s0 += a0[i];
        a1[i] = expf(a1[i] - mx1); s1 += a1[i];
    }
    float i0 = 1.0f / s0, i1 = 1.0f / s1;
    float acc0 = 0.0f, acc1 = 0.0f;
#pragma unroll
    for (int i = 0; i < 16; i++) {
        size_t vb = (size_t)kn[i]*COUT + c;
        float vp0 = g_vall[vb]     + g_pos[base + (size_t)i*COUT];
        float vp1 = g_vall[vb + 1] + g_pos[base + (size_t)i*COUT + 1];
        acc0 = fmaf(a0[i]*i0, vp0, acc0);
        acc1 = fmaf(a1[i]*i1, vp1, acc1);
    }
    uint32_t h, l;
    split2(acc0, acc1, h, l);
    *(uint32_t*)&g_r0h[(size_t)bs*COUT + c] = h;
    *(uint32_t*)&g_r0l[(size_t)bs*COUT + c] = l;
}

// ---------------------------- BatchNorm ------------------------------------
__global__ void bn_partial_kernel()
{
    int blk = blockIdx.x;
    int c   = threadIdx.x;
    float s = 0.0f, q = 0.0f;
    for (int r = blk*128; r < blk*128 + 128; r++) {
        float x = g_res1[(size_t)r*COUT + c];
        s += x; q = fmaf(x, x, q);
    }
    g_psum[blk*COUT + c] = s;
    g_psq [blk*COUT + c] = q;
}

__global__ void bn_final_kernel(const float* __restrict__ bng, const float* __restrict__ bnb)
{
    int c = threadIdx.x;
    float s = 0.0f, q = 0.0f;
    for (int i = 0; i < 64; i++) { s += g_psum[i*COUT + c]; q += g_psq[i*COUT + c]; }
    float mean = s * (1.0f/(float)BSR);
    float var  = fmaxf(q * (1.0f/(float)BSR) - mean*mean, 0.0f);
    float sc   = bng[c] * rsqrtf(var + 1e-5f);
    g_scale[c] = sc;
    g_shift[c] = bnb[c] - mean * sc;
}

__global__ void bn_apply_kernel(float* __restrict__ out)
{
    size_t e = (size_t)blockIdx.x * blockDim.x + threadIdx.x;
    int c = (int)(e & 255);
    out[e] = fmaxf(fmaf(g_res1[e], g_scale[c], g_shift[c]), 0.0f);
}

// ------------------------------ launch --------------------------------------
extern "C" void kernel_launch(void* const* d_in, const int* in_sizes, int n_in,
                              void* d_out, int out_size)
{
    const float* xyz    = (const float*)d_in[0];
    const float* points = (const float*)d_in[1];
    const float* wq     = (const float*)d_in[2];
    const float* wk     = (const float*)d_in[3];
    const float* wv     = (const float*)d_in[4];
    const float* dw1    = (const float*)d_in[5];
    const float* db1    = (const float*)d_in[6];
    const float* dw2    = (const float*)d_in[7];
    const float* db2    = (const float*)d_in[8];
    const float* gw1    = (const float*)d_in[9];
    const float* gb1    = (const float*)d_in[10];
    const float* gw2    = (const float*)d_in[11];
    const float* gb2    = (const float*)d_in[12];
    const float* lw     = (const float*)d_in[13];
    const float* lb     = (const float*)d_in[14];
    const float* bng    = (const float*)d_in[15];
    const float* bnb    = (const float*)d_in[16];

    float* out     = (float*)d_out;
    float* newxyz  = out;
    float* res_out = out + (size_t)BSR*3;

    static bool attr_set = false;
    if (!attr_set) {
        cudaFuncSetAttribute(tgemm_bf,  cudaFuncAttributeMaxDynamicSharedMemorySize, TG_SMEM);
        cudaFuncSetAttribute(fused_all, cudaFuncAttributeMaxDynamicSharedMemorySize, TG_SMEM);
        attr_set = true;
    }

#define SYM(p, s) void* p; cudaGetSymbolAddress(&p, s)
    SYM(ppos, g_pos);  SYM(patt, g_att);
    SYM(pa1h, g_a1h);  SYM(pa1l, g_a1l);
    SYM(px1h, g_x1h);  SYM(px1l, g_x1l);
    SYM(pph,  g_ph);   SYM(ppl,  g_pl);
    SYM(pk,   g_kall); SYM(pv,   g_vall);
    SYM(pq,   g_q);
    SYM(pr0h, g_r0h);  SYM(pr0l, g_r0l);
    SYM(pr1,  g_res1);
    SYM(pknn, g_knn);
    SYM(pdw2h, g_dw2h); SYM(pdw2l, g_dw2l);
    SYM(pgw1h, g_gw1h); SYM(pgw1l, g_gw1l);
    SYM(pgw2h, g_gw2h); SYM(pgw2l, g_gw2l);
    SYM(plwh, g_lwh);   SYM(plwl, g_lwl);
#undef SYM

    // 1: reset progress counters (graph-replay safe)
    reset_prog_kernel<<<1, 64>>>();
    // 2: FPS || pre-cvts || kv GEMM || post-cvts || KNN || q GEMM || h1
    fused_all<<<FUSED_GRID, 256, TG_SMEM>>>(xyz, newxyz, points, wk, wv,
                                            wq, dw2, gw1, gw2, lw, dw1, db1);
    // 3: pos = h1 @ dw2 + db2 (fp32) + fused a1 = q - k_gather + pos (bf16 split)
    tgemm_bf<<<dim3(4, MROWS/128), 256, TG_SMEM>>>(
        (const bf16*)px1h, (const bf16*)px1l, nullptr,
        (const bf16*)pdw2h, (const bf16*)pdw2l, db2, COUT, 0,
        (float*)ppos, nullptr, nullptr,
        (const float*)pq, (const float*)pk, (const int*)pknn,
        (bf16*)pa1h, (bf16*)pa1l);
    // 4: h2 = relu(a1 @ gw1 + gb1) -> x1 (bf16 split)
    tgemm_bf<<<dim3(4, MROWS/128), 256, TG_SMEM>>>(
        (const bf16*)pa1h, (const bf16*)pa1l, nullptr,
        (const bf16*)pgw1h, (const bf16*)pgw1l, gb1, COUT, 1,
        nullptr, (bf16*)px1h, (bf16*)px1l,
        nullptr, nullptr, nullptr, nullptr, nullptr);
    // 5: att = h2 @ gw2 + gb2 -> fp32
    tgemm_bf<<<dim3(4, MROWS/128), 256, TG_SMEM>>>(
        (const bf16*)px1h, (const bf16*)px1l, nullptr,
        (const bf16*)pgw2h, (const bf16*)pgw2l, gb2, COUT, 0,
        (float*)patt, nullptr, nullptr,
        nullptr, nullptr, nullptr, nullptr, nullptr);
    // 6: softmax over K + weighted sum -> r0 (bf16 split)
    softmax_reduce_kernel<<<BSR, 128>>>();
    // 7: res1 = res0 @ lw + lb
    tgemm_bf<<<dim3(4, BSR/128), 256, TG_SMEM>>>(
        (const bf16*)pr0h, (const bf16*)pr0l, nullptr,
        (const bf16*)plwh, (const bf16*)plwl, lb, COUT, 0,
        (float*)pr1, nullptr, nullptr,
        nullptr, nullptr, nullptr, nullptr, nullptr);
    // 8: BatchNorm (training stats) + ReLU -> output
    bn_partial_kernel<<<64, 256>>>();
    bn_final_kernel<<<1, 256>>>(bng, bnb);
    bn_apply_kernel<<<(BSR*COUT)/1024, 1024>>>(res_out);
}